// round 10
// baseline (speedup 1.0000x reference)
#include <cuda_runtime.h>
#include <cuda_bf16.h>
#include <math.h>
#include <cstdint>

#define BATCH 4
#define SEQ   2048
#define EMB   2048
#define HEAD  128
#define NSPLIT 8
#define FL_GRID 288   // 4 batches x 72 (qt,sp) units, <=4 k-tiles each

// ------------------------- device scratch -------------------------
__device__ __nv_bfloat16 g_Xhi[BATCH*SEQ*EMB];
__device__ __nv_bfloat16 g_Xlo[BATCH*SEQ*EMB];
__device__ __nv_bfloat16 g_Bhi[256*EMB];     // rows 0-127: WQ, 128-255: WK
__device__ __nv_bfloat16 g_Blo[256*EMB];
__device__ __nv_bfloat16 g_Vhi[HEAD*EMB];    // W_V as-is: [h][k]
__device__ __nv_bfloat16 g_Vlo[HEAD*EMB];
__device__ __nv_bfloat16 g_Qhi[BATCH*SEQ*HEAD];  // pre-scaled by log2e/sqrt(128)
__device__ __nv_bfloat16 g_Qlo[BATCH*SEQ*HEAD];
__device__ __nv_bfloat16 g_Khi[BATCH*SEQ*HEAD];
__device__ __nv_bfloat16 g_Klo[BATCH*SEQ*HEAD];
__device__ float g_O[NSPLIT][BATCH*SEQ*HEAD];    // unnormalized partial O
__device__ float g_m[NSPLIT][BATCH*SEQ];         // base-2 domain
__device__ float g_l[NSPLIT][BATCH*SEQ];

// ------------------------- helpers -------------------------
__device__ __forceinline__ void cp16s(unsigned sd, const void* gsrc) {
    asm volatile("cp.async.cg.shared.global [%0], [%1], 16;\n" :: "r"(sd), "l"(gsrc));
}
#define CP_COMMIT() asm volatile("cp.async.commit_group;\n" ::: "memory")
#define CP_WAIT(N)  asm volatile("cp.async.wait_group %0;\n" :: "n"(N) : "memory")

__device__ __forceinline__ unsigned smem_u32(const void* p) {
    return (unsigned)__cvta_generic_to_shared((void*)p);
}
__device__ __forceinline__ void ldsm_x4(unsigned addr, unsigned& r0, unsigned& r1,
                                        unsigned& r2, unsigned& r3) {
    asm volatile("ldmatrix.sync.aligned.m8n8.x4.shared.b16 {%0,%1,%2,%3}, [%4];"
                 : "=r"(r0), "=r"(r1), "=r"(r2), "=r"(r3) : "r"(addr));
}
__device__ __forceinline__ void mma_bf16(float* c, const unsigned* a, const unsigned* b) {
    asm volatile(
        "mma.sync.aligned.m16n8k16.row.col.f32.bf16.bf16.f32 "
        "{%0,%1,%2,%3}, {%4,%5,%6,%7}, {%8,%9}, {%0,%1,%2,%3};"
        : "+f"(c[0]), "+f"(c[1]), "+f"(c[2]), "+f"(c[3])
        : "r"(a[0]), "r"(a[1]), "r"(a[2]), "r"(a[3]), "r"(b[0]), "r"(b[1]));
}
__device__ __forceinline__ unsigned cvt2_bf16(float lo_val, float hi_val) {
    unsigned r;
    asm("cvt.rn.bf16x2.f32 %0, %1, %2;" : "=r"(r) : "f"(hi_val), "f"(lo_val));
    return r;
}
__device__ __forceinline__ float bf16_round(float x) {
    return __bfloat162float(__float2bfloat16(x));
}
__device__ __forceinline__ float ex2f(float x) {
    float y; asm("ex2.approx.f32 %0, %1;" : "=f"(y) : "f"(x)); return y;
}

// ---------------------------------------------------------------------------
// convert X -> (hi, lo) bf16 split
// ---------------------------------------------------------------------------
__global__ __launch_bounds__(256) void convert_x_kernel(const float* __restrict__ X)
{
    long i = ((long)blockIdx.x * 256 + threadIdx.x) * 4;
    float4 v = *(const float4*)(X + i);
    float vv[4] = {v.x, v.y, v.z, v.w};
    __nv_bfloat16 hi[4], lo[4];
#pragma unroll
    for (int q = 0; q < 4; q++) {
        hi[q] = __float2bfloat16(vv[q]);
        lo[q] = __float2bfloat16(vv[q] - __bfloat162float(hi[q]));
    }
    *(ushort4*)&g_Xhi[i] = *(ushort4*)hi;
    *(ushort4*)&g_Xlo[i] = *(ushort4*)lo;
}

// ---------------------------------------------------------------------------
// convert WQ/WK/WV
// ---------------------------------------------------------------------------
__global__ __launch_bounds__(256) void convert_wv_kernel(
    const float* __restrict__ WQ, const float* __restrict__ WK,
    const float* __restrict__ WV)
{
    long i = ((long)blockIdx.x * 256 + threadIdx.x) * 4;
    const float* src;
    __nv_bfloat16 *dhi, *dlo;
    long didx;
    if (i < 256L * EMB) {
        int r = (int)(i >> 11);
        long c = i & 2047;
        src = (r < 128) ? (WQ + (long)r * EMB + c) : (WK + (long)(r - 128) * EMB + c);
        dhi = g_Bhi; dlo = g_Blo; didx = i;
    } else {
        long j = i - 256L * EMB;
        src = WV + j;
        dhi = g_Vhi; dlo = g_Vlo; didx = j;
    }
    float4 v = *(const float4*)src;
    float vv[4] = {v.x, v.y, v.z, v.w};
    __nv_bfloat16 hi[4], lo[4];
#pragma unroll
    for (int q = 0; q < 4; q++) {
        hi[q] = __float2bfloat16(vv[q]);
        lo[q] = __float2bfloat16(vv[q] - __bfloat162float(hi[q]));
    }
    *(ushort4*)&dhi[didx] = *(ushort4*)hi;
    *(ushort4*)&dlo[didx] = *(ushort4*)lo;
}

// ---------------------------------------------------------------------------
// mma.sync projection GEMM: Q/K(8192 x 128 each) = X @ B^T (bf16x3 split)
// CTA 128x128 (grid 64 x 2), BK=64, double-buffered cp.async, 8 warps (4m x 2n)
// Per-warp kf rotation desynchronizes LDSM bursts across warps.
// ---------------------------------------------------------------------------
#define PJ_ROWB  144                  // 64 bf16 = 128 B data + 16 B pad
#define PJ_ARR   (128*PJ_ROWB)        // 18432 B per tile array
#define PJ_BUF   (4*PJ_ARR)           // A_hi A_lo B_hi B_lo = 73728 B
#define PJ_SMEM  (2*PJ_BUF)           // 147456 B

__global__ __launch_bounds__(256) void proj_mma_kernel()
{
    extern __shared__ unsigned char dsm8[];
    const unsigned sb = smem_u32(dsm8);

    const int tid = threadIdx.x;
    const int wid = tid >> 5;
    const int lane = tid & 31;
    const int wm = wid & 3;
    const int wn = wid >> 2;

    const int m0 = blockIdx.x * 128;
    const int nt = blockIdx.y;     // 0 -> Q, 1 -> K

    float acc[2][8][4];
#pragma unroll
    for (int m = 0; m < 2; m++)
#pragma unroll
        for (int n = 0; n < 8; n++)
#pragma unroll
            for (int q = 0; q < 4; q++) acc[m][n][q] = 0.f;

    auto load_tile = [&](int buf, int kt) {
        const unsigned base = sb + buf * PJ_BUF;
        const long kof = (long)kt * 64;
        for (int c = tid; c < 1024; c += 256) {
            int r = c >> 3, ch = c & 7;
            unsigned so = (unsigned)(r * PJ_ROWB + ch * 16);
            const long gix = (long)(m0 + r) * EMB + kof + ch * 8;
            cp16s(base + so,          g_Xhi + gix);
            cp16s(base + PJ_ARR + so, g_Xlo + gix);
        }
        for (int c = tid; c < 1024; c += 256) {
            int r = c >> 3, ch = c & 7;
            unsigned so = (unsigned)(r * PJ_ROWB + ch * 16);
            const long gix = (long)(nt * 128 + r) * EMB + kof + ch * 8;
            cp16s(base + 2*PJ_ARR + so, g_Bhi + gix);
            cp16s(base + 3*PJ_ARR + so, g_Blo + gix);
        }
        CP_COMMIT();
    };

    load_tile(0, 0);

    const int a_row_off = (lane & 7) + ((lane >> 3) & 1) * 8;
    const int a_kb_off  = (lane >> 4) * 8;
    const int b_n_off   = (lane & 7) + ((lane >> 3) >> 1) * 8;
    const int b_k_off   = ((lane >> 3) & 1) * 8;

    unsigned ah[2][2][4], al[2][2][4], bh[2][8][2], bl[2][8][2];

    for (int kt = 0; kt < 32; kt++) {
        const int buf = kt & 1;
        __syncthreads();

        if (kt + 1 < 32) {
            load_tile(buf ^ 1, kt + 1);
            CP_WAIT(1);
        } else {
            CP_WAIT(0);
        }
        __syncthreads();

        const unsigned aH = sb + buf * PJ_BUF;
        const unsigned aL = aH + PJ_ARR;
        const unsigned bH = aH + 2*PJ_ARR;
        const unsigned bL = aH + 3*PJ_ARR;

        auto ld_frags = [&](int kf, int pb) {
            const int kb = kf * 16;
#pragma unroll
            for (int m = 0; m < 2; m++) {
                unsigned row = (unsigned)(wm * 32 + m * 16 + a_row_off);
                unsigned off = row * PJ_ROWB + (unsigned)(kb + a_kb_off) * 2;
                ldsm_x4(aH + off, ah[pb][m][0], ah[pb][m][1], ah[pb][m][2], ah[pb][m][3]);
                ldsm_x4(aL + off, al[pb][m][0], al[pb][m][1], al[pb][m][2], al[pb][m][3]);
            }
#pragma unroll
            for (int g = 0; g < 4; g++) {
                unsigned nrow = (unsigned)(wn * 64 + g * 16 + b_n_off);
                unsigned off = nrow * PJ_ROWB + (unsigned)(kb + b_k_off) * 2;
                ldsm_x4(bH + off, bh[pb][g*2][0], bh[pb][g*2][1], bh[pb][g*2+1][0], bh[pb][g*2+1][1]);
                ldsm_x4(bL + off, bl[pb][g*2][0], bl[pb][g*2][1], bl[pb][g*2+1][0], bl[pb][g*2+1][1]);
            }
        };

        // per-warp rotated kf order desyncs warps' LDSM bursts
        ld_frags((0 + wid) & 3, 0);
#pragma unroll
        for (int ki = 0; ki < 4; ki++) {
            const int cur = ki & 1;
            if (ki + 1 < 4) ld_frags((ki + 1 + wid) & 3, cur ^ 1);
#pragma unroll
            for (int m = 0; m < 2; m++)
#pragma unroll
                for (int n = 0; n < 8; n++) mma_bf16(acc[m][n], ah[cur][m], bh[cur][n]);
#pragma unroll
            for (int m = 0; m < 2; m++)
#pragma unroll
                for (int n = 0; n < 8; n++) mma_bf16(acc[m][n], ah[cur][m], bl[cur][n]);
#pragma unroll
            for (int m = 0; m < 2; m++)
#pragma unroll
                for (int n = 0; n < 8; n++) mma_bf16(acc[m][n], al[cur][m], bh[cur][n]);
        }
    }

    // ---- epilogue: write bf16 hi/lo (Q pre-scaled by log2e/sqrt(128)) ----
    __nv_bfloat16* __restrict__ dhi = nt ? g_Khi : g_Qhi;
    __nv_bfloat16* __restrict__ dlo = nt ? g_Klo : g_Qlo;
    const float scl = nt ? 1.0f : (0.08838834764831845f * 1.4426950408889634f);
#pragma unroll
    for (int m = 0; m < 2; m++) {
        const int row = m0 + wm * 32 + m * 16 + (lane >> 2);
#pragma unroll
        for (int n = 0; n < 8; n++) {
            const int col = wn * 64 + n * 8 + (lane & 3) * 2;
            float v0 = acc[m][n][0] * scl, v1 = acc[m][n][1] * scl;
            float v2 = acc[m][n][2] * scl, v3 = acc[m][n][3] * scl;
            *(unsigned*)&dhi[(long)row * HEAD + col] = cvt2_bf16(v0, v1);
            *(unsigned*)&dlo[(long)row * HEAD + col] =
                cvt2_bf16(v0 - bf16_round(v0), v1 - bf16_round(v1));
            *(unsigned*)&dhi[(long)(row + 8) * HEAD + col] = cvt2_bf16(v2, v3);
            *(unsigned*)&dlo[(long)(row + 8) * HEAD + col] =
                cvt2_bf16(v2 - bf16_round(v2), v3 - bf16_round(v3));
        }
    }
}

// ---------------------------------------------------------------------------
// Tensor-core causal flash attention, bf16x3 split, balanced variable split-K.
// CTA: 128 q-rows x (<=4) 64-wide k-tiles. Base-2 softmax domain.
// ---------------------------------------------------------------------------
#define FL_QROWB 272
#define FL_KROWB 272
#define FL_VROWB 144
#define FL_QH 0
#define FL_QL 34816
#define FL_KB 69632
#define FL_VB 139264
#define FL_SMEM 212992

__global__ __launch_bounds__(256) void flash_kernel()
{
    extern __shared__ unsigned char dsm8[];
    const unsigned sb = smem_u32(dsm8);

    const int tid = threadIdx.x;
    const int wm  = tid >> 5;
    const int lane = tid & 31;

    // decode bid -> (qt heavy-first, b, sp)
    const int bid = blockIdx.x;
    const int u = bid >> 2;
    const int b = bid & 3;
    int qt = 0, sp = 0;
    {
        int acc = 0;
        for (int q = 15; q >= 0; q--) {
            int ns = (q + 2) >> 1;
            if (u < acc + ns) { qt = q; sp = u - acc; break; }
            acc += ns;
        }
    }
    const int nkt   = 2 * (qt + 1);
    const int kt_lo = sp * 4;
    const int kt_hi = min(nkt, kt_lo + 4);

    const long qrow0 = (long)b * SEQ + qt * 128;

    for (int c = tid; c < 2048; c += 256) {
        int r = c >> 4, ch = c & 15;
        unsigned so = (unsigned)(r * FL_QROWB + ch * 16);
        const long gix = (qrow0 + r) * HEAD + ch * 8;
        cp16s(sb + FL_QH + so, g_Qhi + gix);
        cp16s(sb + FL_QL + so, g_Qlo + gix);
    }

    auto load_kv = [&](int buf, int kt) {
        const unsigned kh = sb + FL_KB + buf * 34816;
        const unsigned vh = sb + FL_VB + buf * 36864;
        for (int c = tid; c < 1024; c += 256) {
            int r = c >> 4, ch = c & 15;
            unsigned so = (unsigned)(r * FL_KROWB + ch * 16);
            const long gix = ((long)b * SEQ + kt * 64 + r) * HEAD + ch * 8;
            cp16s(kh + so,         g_Khi + gix);
            cp16s(kh + 17408 + so, g_Klo + gix);
        }
        for (int c = tid; c < 1024; c += 256) {
            int r = c >> 3, ch = c & 7;
            unsigned so = (unsigned)(r * FL_VROWB + ch * 16);
            const long gix = (long)r * EMB + kt * 64 + ch * 8;
            cp16s(vh + so,         g_Vhi + gix);
            cp16s(vh + 18432 + so, g_Vlo + gix);
        }
        CP_COMMIT();
    };

    load_kv(0, kt_lo);

    float o[16][4];
#pragma unroll
    for (int n = 0; n < 16; n++)
#pragma unroll
        for (int q = 0; q < 4; q++) o[n][q] = 0.f;
    float m0 = -1e30f, m1 = -1e30f;
    float l0 = 0.f, l1 = 0.f;

    const int a_row_off = (lane & 7) + ((lane >> 3) & 1) * 8;
    const int a_kb_off  = (lane >> 4) * 8;
    const int b_n_off   = (lane & 7) + ((lane >> 3) >> 1) * 8;
    const int b_k_off   = ((lane >> 3) & 1) * 8;

    for (int kt = kt_lo; kt < kt_hi; kt++) {
        const int buf = (kt - kt_lo) & 1;
        __syncthreads();

        if (kt + 1 < kt_hi) {
            load_kv(buf ^ 1, kt + 1);
            CP_WAIT(1);
        } else {
            CP_WAIT(0);
        }
        __syncthreads();

        const unsigned kH = sb + FL_KB + buf * 34816;
        const unsigned kL = kH + 17408;
        const unsigned vH = sb + FL_VB + buf * 36864;
        const unsigned vL = vH + 18432;

        // ---- S = Q K^T (per-warp rotated t order) ----
        float s[8][4];
#pragma unroll
        for (int n = 0; n < 8; n++)
#pragma unroll
            for (int q = 0; q < 4; q++) s[n][q] = 0.f;

        unsigned ah[2][4], al[2][4], bh[2][4][4], bl[2][4][4];

        auto ld_sfrags = [&](int t, int pb) {
            const int kb = t * 16;
            unsigned aoff = (unsigned)((wm * 16 + a_row_off) * FL_QROWB + (kb + a_kb_off) * 2);
            ldsm_x4(sb + FL_QH + aoff, ah[pb][0], ah[pb][1], ah[pb][2], ah[pb][3]);
            ldsm_x4(sb + FL_QL + aoff, al[pb][0], al[pb][1], al[pb][2], al[pb][3]);
#pragma unroll
            for (int g = 0; g < 4; g++) {
                unsigned boff = (unsigned)((g * 16 + b_n_off) * FL_KROWB + (kb + b_k_off) * 2);
                ldsm_x4(kH + boff, bh[pb][g][0], bh[pb][g][1], bh[pb][g][2], bh[pb][g][3]);
                ldsm_x4(kL + boff, bl[pb][g][0], bl[pb][g][1], bl[pb][g][2], bl[pb][g][3]);
            }
        };

        ld_sfrags(wm, 0);
#pragma unroll
        for (int ti = 0; ti < 8; ti++) {
            const int cur = ti & 1;
            if (ti + 1 < 8) ld_sfrags((ti + 1 + wm) & 7, cur ^ 1);
#pragma unroll
            for (int g = 0; g < 4; g++) {
                mma_bf16(s[2*g],   ah[cur], bh[cur][g]);
                mma_bf16(s[2*g+1], ah[cur], bh[cur][g] + 2);
            }
#pragma unroll
            for (int g = 0; g < 4; g++) {
                mma_bf16(s[2*g],   ah[cur], bl[cur][g]);
                mma_bf16(s[2*g+1], ah[cur], bl[cur][g] + 2);
            }
#pragma unroll
            for (int g = 0; g < 4; g++) {
                mma_bf16(s[2*g],   al[cur], bh[cur][g]);
                mma_bf16(s[2*g+1], al[cur], bh[cur][g] + 2);
            }
        }

        // ---- causal mask ----
        const int qr0 = qt * 128 + wm * 16 + (lane >> 2);
        const int qr1 = qr0 + 8;
        if (kt * 64 + 63 > qt * 128 + wm * 16) {
#pragma unroll
            for (int n = 0; n < 8; n++) {
                int c0 = kt * 64 + n * 8 + (lane & 3) * 2;
                if (c0     > qr0) s[n][0] = -1e30f;
                if (c0 + 1 > qr0) s[n][1] = -1e30f;
                if (c0     > qr1) s[n][2] = -1e30f;
                if (c0 + 1 > qr1) s[n][3] = -1e30f;
            }
        }

        // ---- online softmax (base-2 domain) ----
        float mx0 = -1e30f, mx1 = -1e30f;
#pragma unroll
        for (int n = 0; n < 8; n++) {
            mx0 = fmaxf(mx0, fmaxf(s[n][0], s[n][1]));
            mx1 = fmaxf(mx1, fmaxf(s[n][2], s[n][3]));
        }
        mx0 = fmaxf(mx0, __shfl_xor_sync(0xffffffffu, mx0, 1));
        mx0 = fmaxf(mx0, __shfl_xor_sync(0xffffffffu, mx0, 2));
        mx1 = fmaxf(mx1, __shfl_xor_sync(0xffffffffu, mx1, 1));
        mx1 = fmaxf(mx1, __shfl_xor_sync(0xffffffffu, mx1, 2));

        const float mn0 = fmaxf(m0, mx0);
        const float mn1 = fmaxf(m1, mx1);
        const float fac0 = ex2f(m0 - mn0);
        const float fac1 = ex2f(m1 - mn1);

        unsigned pAh[4][4], pAl[4][4];
        float ls0 = 0.f, ls1 = 0.f;
#pragma unroll
        for (int t = 0; t < 4; t++) {
            float p00 = ex2f(s[2*t][0] - mn0),   p01 = ex2f(s[2*t][1] - mn0);
            float p02 = ex2f(s[2*t][2] - mn1),   p03 = ex2f(s[2*t][3] - mn1);
            float p10 = ex2f(s[2*t+1][0] - mn0), p11 = ex2f(s[2*t+1][1] - mn0);
            float p12 = ex2f(s[2*t+1][2] - mn1), p13 = ex2f(s[2*t+1][3] - mn1);
            ls0 += (p00 + p01) + (p10 + p11);
            ls1 += (p02 + p03) + (p12 + p13);
            pAh[t][0] = cvt2_bf16(p00, p01);
            pAh[t][1] = cvt2_bf16(p02, p03);
            pAh[t][2] = cvt2_bf16(p10, p11);
            pAh[t][3] = cvt2_bf16(p12, p13);
            pAl[t][0] = cvt2_bf16(p00 - bf16_round(p00), p01 - bf16_round(p01));
            pAl[t][1] = cvt2_bf16(p02 - bf16_round(p02), p03 - bf16_round(p03));
            pAl[t][2] = cvt2_bf16(p10 - bf16_round(p10), p11 - bf16_round(p11));
            pAl[t][3] = cvt2_bf16(p12 - bf16_round(p12), p13 - bf16_round(p13));
        }
        l0 = l0 * fac0 + ls0;
        l1 = l1 * fac1 + ls1;
        m0 = mn0; m1 = mn1;
#pragma unroll
        for (int n = 0; n < 16; n++) {
            o[n][0] *= fac0; o[n][1] *= fac0;
            o[n][2] *= fac1; o[n][3] *= fac1;
        }

        // ---- O += P @ V (per-warp rotated t order) ----
#pragma unroll
        for (int ti = 0; ti < 4; ti++) {
            const int t = (ti + wm) & 3;
#pragma unroll
            for (int h = 0; h < 2; h++) {
                unsigned vhr[4][4], vlr[4][4];
#pragma unroll
                for (int g4 = 0; g4 < 4; g4++) {
                    const int g = h * 4 + g4;
                    unsigned boff = (unsigned)((g * 16 + b_n_off) * FL_VROWB + (t * 16 + b_k_off) * 2);
                    ldsm_x4(vH + boff, vhr[g4][0], vhr[g4][1], vhr[g4][2], vhr[g4][3]);
                    ldsm_x4(vL + boff, vlr[g4][0], vlr[g4][1], vlr[g4][2], vlr[g4][3]);
                }
#pragma unroll
                for (int g4 = 0; g4 < 4; g4++) {
                    const int g = h * 4 + g4;
                    mma_bf16(o[2*g],   pAh[t], vhr[g4]);
                    mma_bf16(o[2*g+1], pAh[t], vhr[g4] + 2);
                }
#pragma unroll
                for (int g4 = 0; g4 < 4; g4++) {
                    const int g = h * 4 + g4;
                    mma_bf16(o[2*g],   pAh[t], vlr[g4]);
                    mma_bf16(o[2*g+1], pAh[t], vlr[g4] + 2);
                }
#pragma unroll
                for (int g4 = 0; g4 < 4; g4++) {
                    const int g = h * 4 + g4;
                    mma_bf16(o[2*g],   pAl[t], vhr[g4]);
                    mma_bf16(o[2*g+1], pAl[t], vhr[g4] + 2);
                }
            }
        }
    }

    // ---- epilogue ----
    l0 += __shfl_xor_sync(0xffffffffu, l0, 1);
    l0 += __shfl_xor_sync(0xffffffffu, l0, 2);
    l1 += __shfl_xor_sync(0xffffffffu, l1, 1);
    l1 += __shfl_xor_sync(0xffffffffu, l1, 2);

    const int r0 = wm * 16 + (lane >> 2);
    float* __restrict__ Og = g_O[sp] + (qrow0) * HEAD;
#pragma unroll
    for (int n = 0; n < 16; n++) {
        const int col = n * 8 + (lane & 3) * 2;
        *(float2*)&Og[(long)r0 * HEAD + col]       = make_float2(o[n][0], o[n][1]);
        *(float2*)&Og[(long)(r0 + 8) * HEAD + col] = make_float2(o[n][2], o[n][3]);
    }
    if ((lane & 3) == 0) {
        const long rowg = (long)b * SEQ + qt * 128 + r0;
        g_m[sp][rowg] = m0;     g_l[sp][rowg] = l0;
        g_m[sp][rowg + 8] = m1; g_l[sp][rowg + 8] = l1;
    }
}

// ---------------------------------------------------------------------------
// Combine variable splits: out = sum_s w_s O_s / sum_s w_s l_s (base-2 weights)
// float4 vectorized: each thread owns 4 consecutive h of one row.
// ---------------------------------------------------------------------------
__global__ __launch_bounds__(256) void combine_kernel(float* __restrict__ out)
{
    const int id = blockIdx.x * 256 + threadIdx.x;   // 0 .. B*S*H/4-1
    const long base = (long)id * 4;
    const int row = (int)(base >> 7);
    const int qt = (row & 2047) >> 7;
    const int ns = (qt + 2) >> 1;

    float M = -1e30f;
    for (int s = 0; s < ns; s++) M = fmaxf(M, g_m[s][row]);

    float4 num = make_float4(0.f, 0.f, 0.f, 0.f);
    float den = 0.f;
    for (int s = 0; s < ns; s++) {
        float w = ex2f(g_m[s][row] - M);
        float4 ov = *(const float4*)&g_O[s][base];
        num.x += w * ov.x; num.y += w * ov.y;
        num.z += w * ov.z; num.w += w * ov.w;
        den += w * g_l[s][row];
    }
    float inv = 1.0f / den;
    *(float4*)&out[base] = make_float4(num.x*inv, num.y*inv, num.z*inv, num.w*inv);
}

// ---------------------------------------------------------------------------
extern "C" void kernel_launch(void* const* d_in, const int* in_sizes, int n_in,
                              void* d_out, int out_size)
{
    const float* X  = (const float*)d_in[0];
    const float* WQ = (const float*)d_in[1];
    const float* WK = (const float*)d_in[2];
    const float* WV = (const float*)d_in[3];
    float* out = (float*)d_out;

    cudaFuncSetAttribute(proj_mma_kernel,
                         cudaFuncAttributeMaxDynamicSharedMemorySize, PJ_SMEM);
    cudaFuncSetAttribute(flash_kernel,
                         cudaFuncAttributeMaxDynamicSharedMemorySize, FL_SMEM);

    convert_x_kernel<<<(BATCH*SEQ*EMB)/1024, 256>>>(X);                  // 0
    convert_wv_kernel<<<(384*EMB)/1024, 256>>>(WQ, WK, WV);              // 1
    proj_mma_kernel<<<dim3(64, 2), 256, PJ_SMEM>>>();                    // 2
    flash_kernel<<<FL_GRID, 256, FL_SMEM>>>();                           // 3
    combine_kernel<<<(BATCH*SEQ*HEAD/4)/256, 256>>>(out);                // 4
}

// round 11
// speedup vs baseline: 1.0111x; 1.0111x over previous
#include <cuda_runtime.h>
#include <cuda_bf16.h>
#include <math.h>
#include <cstdint>

#define BATCH 4
#define SEQ   2048
#define EMB   2048
#define HEAD  128
#define NSPLIT 4

// ------------------------- device scratch -------------------------
__device__ __nv_bfloat16 g_Xhi[BATCH*SEQ*EMB];
__device__ __nv_bfloat16 g_Xlo[BATCH*SEQ*EMB];
__device__ __nv_bfloat16 g_Bhi[256*EMB];     // rows 0-127: WQ, 128-255: WK
__device__ __nv_bfloat16 g_Blo[256*EMB];
__device__ __nv_bfloat16 g_Vhi[HEAD*EMB];    // W_V as-is: [h][k]
__device__ __nv_bfloat16 g_Vlo[HEAD*EMB];
__device__ __nv_bfloat16 g_Qhi[BATCH*SEQ*HEAD];  // pre-scaled by log2e/sqrt(128)
__device__ __nv_bfloat16 g_Qlo[BATCH*SEQ*HEAD];
__device__ __nv_bfloat16 g_Khi[BATCH*SEQ*HEAD];
__device__ __nv_bfloat16 g_Klo[BATCH*SEQ*HEAD];
__device__ float g_P[2][BATCH*SEQ*256];          // proj K-split partials (fp32)
__device__ float g_O[NSPLIT][BATCH*SEQ*HEAD];    // unnormalized partial O
__device__ float g_m[NSPLIT][BATCH*SEQ];         // base-2 domain
__device__ float g_l[NSPLIT][BATCH*SEQ];

// ------------------------- helpers -------------------------
__device__ __forceinline__ void cp16s(unsigned sd, const void* gsrc) {
    asm volatile("cp.async.cg.shared.global [%0], [%1], 16;\n" :: "r"(sd), "l"(gsrc));
}
#define CP_COMMIT() asm volatile("cp.async.commit_group;\n" ::: "memory")
#define CP_WAIT(N)  asm volatile("cp.async.wait_group %0;\n" :: "n"(N) : "memory")

__device__ __forceinline__ unsigned smem_u32(const void* p) {
    return (unsigned)__cvta_generic_to_shared((void*)p);
}
__device__ __forceinline__ void ldsm_x4(unsigned addr, unsigned& r0, unsigned& r1,
                                        unsigned& r2, unsigned& r3) {
    asm volatile("ldmatrix.sync.aligned.m8n8.x4.shared.b16 {%0,%1,%2,%3}, [%4];"
                 : "=r"(r0), "=r"(r1), "=r"(r2), "=r"(r3) : "r"(addr));
}
__device__ __forceinline__ void mma_bf16(float* c, const unsigned* a, const unsigned* b) {
    asm volatile(
        "mma.sync.aligned.m16n8k16.row.col.f32.bf16.bf16.f32 "
        "{%0,%1,%2,%3}, {%4,%5,%6,%7}, {%8,%9}, {%0,%1,%2,%3};"
        : "+f"(c[0]), "+f"(c[1]), "+f"(c[2]), "+f"(c[3])
        : "r"(a[0]), "r"(a[1]), "r"(a[2]), "r"(a[3]), "r"(b[0]), "r"(b[1]));
}
__device__ __forceinline__ unsigned cvt2_bf16(float lo_val, float hi_val) {
    unsigned r;
    asm("cvt.rn.bf16x2.f32 %0, %1, %2;" : "=r"(r) : "f"(hi_val), "f"(lo_val));
    return r;
}
__device__ __forceinline__ float bf16_round(float x) {
    return __bfloat162float(__float2bfloat16(x));
}
__device__ __forceinline__ float ex2f(float x) {
    float y; asm("ex2.approx.f32 %0, %1;" : "=f"(y) : "f"(x)); return y;
}

// ---------------------------------------------------------------------------
// convert X -> (hi, lo) bf16 split
// ---------------------------------------------------------------------------
__global__ __launch_bounds__(256) void convert_x_kernel(const float* __restrict__ X)
{
    long i = ((long)blockIdx.x * 256 + threadIdx.x) * 4;
    float4 v = *(const float4*)(X + i);
    float vv[4] = {v.x, v.y, v.z, v.w};
    __nv_bfloat16 hi[4], lo[4];
#pragma unroll
    for (int q = 0; q < 4; q++) {
        hi[q] = __float2bfloat16(vv[q]);
        lo[q] = __float2bfloat16(vv[q] - __bfloat162float(hi[q]));
    }
    *(ushort4*)&g_Xhi[i] = *(ushort4*)hi;
    *(ushort4*)&g_Xlo[i] = *(ushort4*)lo;
}

// ---------------------------------------------------------------------------
// convert WQ/WK/WV
// ---------------------------------------------------------------------------
__global__ __launch_bounds__(256) void convert_wv_kernel(
    const float* __restrict__ WQ, const float* __restrict__ WK,
    const float* __restrict__ WV)
{
    long i = ((long)blockIdx.x * 256 + threadIdx.x) * 4;
    const float* src;
    __nv_bfloat16 *dhi, *dlo;
    long didx;
    if (i < 256L * EMB) {
        int r = (int)(i >> 11);
        long c = i & 2047;
        src = (r < 128) ? (WQ + (long)r * EMB + c) : (WK + (long)(r - 128) * EMB + c);
        dhi = g_Bhi; dlo = g_Blo; didx = i;
    } else {
        long j = i - 256L * EMB;
        src = WV + j;
        dhi = g_Vhi; dlo = g_Vlo; didx = j;
    }
    float4 v = *(const float4*)src;
    float vv[4] = {v.x, v.y, v.z, v.w};
    __nv_bfloat16 hi[4], lo[4];
#pragma unroll
    for (int q = 0; q < 4; q++) {
        hi[q] = __float2bfloat16(vv[q]);
        lo[q] = __float2bfloat16(vv[q] - __bfloat162float(hi[q]));
    }
    *(ushort4*)&dhi[didx] = *(ushort4*)hi;
    *(ushort4*)&dlo[didx] = *(ushort4*)lo;
}

// ---------------------------------------------------------------------------
// mma.sync projection GEMM, K-split 2: partial[z] = X[:, z*1024:(z+1)*1024] @ B^T
// CTA 128x128 (grid 64 x 2 x 2), BK=32, double-buffered cp.async.
// 82KB smem + <=128 regs -> 2 CTAs/SM co-resident.
// ---------------------------------------------------------------------------
#define PJ_ROWB  80                   // 32 bf16 = 64 B data + 16 B pad
#define PJ_ARR   (128*PJ_ROWB)        // 10240 B per tile array
#define PJ_BUF   (4*PJ_ARR)           // A_hi A_lo B_hi B_lo = 40960 B
#define PJ_SMEM  (2*PJ_BUF)           // 81920 B

__global__ __launch_bounds__(256, 2) void proj_mma_kernel()
{
    extern __shared__ unsigned char dsm8[];
    const unsigned sb = smem_u32(dsm8);

    const int tid = threadIdx.x;
    const int wid = tid >> 5;
    const int lane = tid & 31;
    const int wm = wid & 3;
    const int wn = wid >> 2;

    const int m0 = blockIdx.x * 128;
    const int nt = blockIdx.y;     // 0 -> Q cols, 1 -> K cols
    const int kz = blockIdx.z;     // K half
    const long kbase = (long)kz * 1024;

    float acc[2][8][4];
#pragma unroll
    for (int m = 0; m < 2; m++)
#pragma unroll
        for (int n = 0; n < 8; n++)
#pragma unroll
            for (int q = 0; q < 4; q++) acc[m][n][q] = 0.f;

    auto load_tile = [&](int buf, int kt) {
        const unsigned base = sb + buf * PJ_BUF;
        const long kof = kbase + (long)kt * 32;
        for (int c = tid; c < 512; c += 256) {
            int r = c >> 2, ch = c & 3;
            unsigned so = (unsigned)(r * PJ_ROWB + ch * 16);
            const long gix = (long)(m0 + r) * EMB + kof + ch * 8;
            cp16s(base + so,          g_Xhi + gix);
            cp16s(base + PJ_ARR + so, g_Xlo + gix);
        }
        for (int c = tid; c < 512; c += 256) {
            int r = c >> 2, ch = c & 3;
            unsigned so = (unsigned)(r * PJ_ROWB + ch * 16);
            const long gix = (long)(nt * 128 + r) * EMB + kof + ch * 8;
            cp16s(base + 2*PJ_ARR + so, g_Bhi + gix);
            cp16s(base + 3*PJ_ARR + so, g_Blo + gix);
        }
        CP_COMMIT();
    };

    load_tile(0, 0);

    const int a_row_off = (lane & 7) + ((lane >> 3) & 1) * 8;
    const int a_kb_off  = (lane >> 4) * 8;
    const int b_n_off   = (lane & 7) + ((lane >> 3) >> 1) * 8;
    const int b_k_off   = ((lane >> 3) & 1) * 8;

    for (int kt = 0; kt < 32; kt++) {
        const int buf = kt & 1;
        __syncthreads();

        if (kt + 1 < 32) {
            load_tile(buf ^ 1, kt + 1);
            CP_WAIT(1);
        } else {
            CP_WAIT(0);
        }
        __syncthreads();

        const unsigned aH = sb + buf * PJ_BUF;
        const unsigned aL = aH + PJ_ARR;
        const unsigned bH = aH + 2*PJ_ARR;
        const unsigned bL = aH + 3*PJ_ARR;

#pragma unroll
        for (int kf = 0; kf < 2; kf++) {
            const int kb = kf * 16;
            unsigned ah[2][4], al[2][4];
#pragma unroll
            for (int m = 0; m < 2; m++) {
                unsigned row = (unsigned)(wm * 32 + m * 16 + a_row_off);
                unsigned off = row * PJ_ROWB + (unsigned)(kb + a_kb_off) * 2;
                ldsm_x4(aH + off, ah[m][0], ah[m][1], ah[m][2], ah[m][3]);
                ldsm_x4(aL + off, al[m][0], al[m][1], al[m][2], al[m][3]);
            }
            unsigned bh[8][2], bl[8][2];
#pragma unroll
            for (int g = 0; g < 4; g++) {
                unsigned nrow = (unsigned)(wn * 64 + g * 16 + b_n_off);
                unsigned off = nrow * PJ_ROWB + (unsigned)(kb + b_k_off) * 2;
                ldsm_x4(bH + off, bh[g*2][0], bh[g*2][1], bh[g*2+1][0], bh[g*2+1][1]);
                ldsm_x4(bL + off, bl[g*2][0], bl[g*2][1], bl[g*2+1][0], bl[g*2+1][1]);
            }
#pragma unroll
            for (int m = 0; m < 2; m++)
#pragma unroll
                for (int n = 0; n < 8; n++) mma_bf16(acc[m][n], ah[m], bh[n]);
#pragma unroll
            for (int m = 0; m < 2; m++)
#pragma unroll
                for (int n = 0; n < 8; n++) mma_bf16(acc[m][n], ah[m], bl[n]);
#pragma unroll
            for (int m = 0; m < 2; m++)
#pragma unroll
                for (int n = 0; n < 8; n++) mma_bf16(acc[m][n], al[m], bh[n]);
        }
    }

    // ---- epilogue: write fp32 partials ----
    float* __restrict__ P = g_P[kz];
#pragma unroll
    for (int m = 0; m < 2; m++) {
        const int row = m0 + wm * 32 + m * 16 + (lane >> 2);
#pragma unroll
        for (int n = 0; n < 8; n++) {
            const int col = nt * 128 + wn * 64 + n * 8 + (lane & 3) * 2;
            *(float2*)&P[(long)row * 256 + col] = make_float2(acc[m][n][0], acc[m][n][1]);
            *(float2*)&P[(long)(row + 8) * 256 + col] = make_float2(acc[m][n][2], acc[m][n][3]);
        }
    }
}

// ---------------------------------------------------------------------------
// Reduce K-split partials -> bf16 hi/lo Q (log2e-prescaled) and K
// ---------------------------------------------------------------------------
__global__ __launch_bounds__(256) void proj_reduce_kernel()
{
    const long base = ((long)blockIdx.x * 256 + threadIdx.x) * 4;
    const int row = (int)(base >> 8);
    const int col = (int)(base & 255);
    const float qscl = 0.08838834764831845f * 1.4426950408889634f;

    float4 a = *(const float4*)&g_P[0][base];
    float4 c = *(const float4*)&g_P[1][base];
    float s[4] = {a.x + c.x, a.y + c.y, a.z + c.z, a.w + c.w};

    __nv_bfloat16 *dhi, *dlo;
    long didx;
    float scl;
    if (col < 128) { dhi = g_Qhi; dlo = g_Qlo; didx = (long)row * HEAD + col; scl = qscl; }
    else           { dhi = g_Khi; dlo = g_Klo; didx = (long)row * HEAD + (col - 128); scl = 1.0f; }

    unsigned hw[2], lw[2];
#pragma unroll
    for (int p = 0; p < 2; p++) {
        float v0 = s[p*2] * scl, v1 = s[p*2+1] * scl;
        hw[p] = cvt2_bf16(v0, v1);
        lw[p] = cvt2_bf16(v0 - bf16_round(v0), v1 - bf16_round(v1));
    }
    *(uint2*)&dhi[didx] = make_uint2(hw[0], hw[1]);
    *(uint2*)&dlo[didx] = make_uint2(lw[0], lw[1]);
}

// ---------------------------------------------------------------------------
// Tensor-core causal flash attention, bf16x3 split, split-K(4). (R9 structure,
// base-2 softmax domain.)
// ---------------------------------------------------------------------------
#define FL_QROWB 272
#define FL_KROWB 272
#define FL_VROWB 144
#define FL_QH 0
#define FL_QL 34816
#define FL_KB 69632
#define FL_VB 139264
#define FL_SMEM 212992

__global__ __launch_bounds__(256) void flash_kernel()
{
    extern __shared__ unsigned char dsm8[];
    const unsigned sb = smem_u32(dsm8);

    const int tid = threadIdx.x;
    const int wm  = tid >> 5;
    const int lane = tid & 31;

    const int bid = blockIdx.x;
    const int qt = 15 - (bid >> 4);
    const int b  = (bid >> 2) & 3;
    const int sp = bid & 3;

    const int nkt   = 2 * (qt + 1);
    const int chunk = (nkt + NSPLIT - 1) / NSPLIT;
    const int kt_lo = sp * chunk;
    const int kt_hi = min(nkt, kt_lo + chunk);

    const long qrow0 = (long)b * SEQ + qt * 128;

    for (int c = tid; c < 2048; c += 256) {
        int r = c >> 4, ch = c & 15;
        unsigned so = (unsigned)(r * FL_QROWB + ch * 16);
        const long gix = (qrow0 + r) * HEAD + ch * 8;
        cp16s(sb + FL_QH + so, g_Qhi + gix);
        cp16s(sb + FL_QL + so, g_Qlo + gix);
    }

    auto load_kv = [&](int buf, int kt) {
        const unsigned kh = sb + FL_KB + buf * 34816;
        const unsigned vh = sb + FL_VB + buf * 36864;
        for (int c = tid; c < 1024; c += 256) {
            int r = c >> 4, ch = c & 15;
            unsigned so = (unsigned)(r * FL_KROWB + ch * 16);
            const long gix = ((long)b * SEQ + kt * 64 + r) * HEAD + ch * 8;
            cp16s(kh + so,         g_Khi + gix);
            cp16s(kh + 17408 + so, g_Klo + gix);
        }
        for (int c = tid; c < 1024; c += 256) {
            int r = c >> 3, ch = c & 7;
            unsigned so = (unsigned)(r * FL_VROWB + ch * 16);
            const long gix = (long)r * EMB + kt * 64 + ch * 8;
            cp16s(vh + so,         g_Vhi + gix);
            cp16s(vh + 18432 + so, g_Vlo + gix);
        }
        CP_COMMIT();
    };

    if (kt_lo < kt_hi) load_kv(0, kt_lo);
    else CP_COMMIT();

    float o[16][4];
#pragma unroll
    for (int n = 0; n < 16; n++)
#pragma unroll
        for (int q = 0; q < 4; q++) o[n][q] = 0.f;
    float m0 = -1e30f, m1 = -1e30f;
    float l0 = 0.f, l1 = 0.f;

    const int a_row_off = (lane & 7) + ((lane >> 3) & 1) * 8;
    const int a_kb_off  = (lane >> 4) * 8;
    const int b_n_off   = (lane & 7) + ((lane >> 3) >> 1) * 8;
    const int b_k_off   = ((lane >> 3) & 1) * 8;

    for (int kt = kt_lo; kt < kt_hi; kt++) {
        const int buf = (kt - kt_lo) & 1;
        __syncthreads();

        if (kt + 1 < kt_hi) {
            load_kv(buf ^ 1, kt + 1);
            CP_WAIT(1);
        } else {
            CP_WAIT(0);
        }
        __syncthreads();

        const unsigned kH = sb + FL_KB + buf * 34816;
        const unsigned kL = kH + 17408;
        const unsigned vH = sb + FL_VB + buf * 36864;
        const unsigned vL = vH + 18432;

        // ---- S = Q K^T (fragment-pipelined over t) ----
        float s[8][4];
#pragma unroll
        for (int n = 0; n < 8; n++)
#pragma unroll
            for (int q = 0; q < 4; q++) s[n][q] = 0.f;

        unsigned ah[2][4], al[2][4], bh[2][4][4], bl[2][4][4];

        auto ld_sfrags = [&](int t, int pb) {
            const int kb = t * 16;
            unsigned aoff = (unsigned)((wm * 16 + a_row_off) * FL_QROWB + (kb + a_kb_off) * 2);
            ldsm_x4(sb + FL_QH + aoff, ah[pb][0], ah[pb][1], ah[pb][2], ah[pb][3]);
            ldsm_x4(sb + FL_QL + aoff, al[pb][0], al[pb][1], al[pb][2], al[pb][3]);
#pragma unroll
            for (int g = 0; g < 4; g++) {
                unsigned boff = (unsigned)((g * 16 + b_n_off) * FL_KROWB + (kb + b_k_off) * 2);
                ldsm_x4(kH + boff, bh[pb][g][0], bh[pb][g][1], bh[pb][g][2], bh[pb][g][3]);
                ldsm_x4(kL + boff, bl[pb][g][0], bl[pb][g][1], bl[pb][g][2], bl[pb][g][3]);
            }
        };

        ld_sfrags(0, 0);
#pragma unroll
        for (int t = 0; t < 8; t++) {
            const int cur = t & 1;
            if (t + 1 < 8) ld_sfrags(t + 1, cur ^ 1);
#pragma unroll
            for (int g = 0; g < 4; g++) {
                mma_bf16(s[2*g],   ah[cur], bh[cur][g]);
                mma_bf16(s[2*g+1], ah[cur], bh[cur][g] + 2);
            }
#pragma unroll
            for (int g = 0; g < 4; g++) {
                mma_bf16(s[2*g],   ah[cur], bl[cur][g]);
                mma_bf16(s[2*g+1], ah[cur], bl[cur][g] + 2);
            }
#pragma unroll
            for (int g = 0; g < 4; g++) {
                mma_bf16(s[2*g],   al[cur], bh[cur][g]);
                mma_bf16(s[2*g+1], al[cur], bh[cur][g] + 2);
            }
        }

        // ---- causal mask ----
        const int qr0 = qt * 128 + wm * 16 + (lane >> 2);
        const int qr1 = qr0 + 8;
        if (kt * 64 + 63 > qt * 128 + wm * 16) {
#pragma unroll
            for (int n = 0; n < 8; n++) {
                int c0 = kt * 64 + n * 8 + (lane & 3) * 2;
                if (c0     > qr0) s[n][0] = -1e30f;
                if (c0 + 1 > qr0) s[n][1] = -1e30f;
                if (c0     > qr1) s[n][2] = -1e30f;
                if (c0 + 1 > qr1) s[n][3] = -1e30f;
            }
        }

        // ---- online softmax (base-2 domain) ----
        float mx0 = -1e30f, mx1 = -1e30f;
#pragma unroll
        for (int n = 0; n < 8; n++) {
            mx0 = fmaxf(mx0, fmaxf(s[n][0], s[n][1]));
            mx1 = fmaxf(mx1, fmaxf(s[n][2], s[n][3]));
        }
        mx0 = fmaxf(mx0, __shfl_xor_sync(0xffffffffu, mx0, 1));
        mx0 = fmaxf(mx0, __shfl_xor_sync(0xffffffffu, mx0, 2));
        mx1 = fmaxf(mx1, __shfl_xor_sync(0xffffffffu, mx1, 1));
        mx1 = fmaxf(mx1, __shfl_xor_sync(0xffffffffu, mx1, 2));

        const float mn0 = fmaxf(m0, mx0);
        const float mn1 = fmaxf(m1, mx1);
        const float fac0 = ex2f(m0 - mn0);
        const float fac1 = ex2f(m1 - mn1);

        unsigned pAh[4][4], pAl[4][4];
        float ls0 = 0.f, ls1 = 0.f;
#pragma unroll
        for (int t = 0; t < 4; t++) {
            float p00 = ex2f(s[2*t][0] - mn0),   p01 = ex2f(s[2*t][1] - mn0);
            float p02 = ex2f(s[2*t][2] - mn1),   p03 = ex2f(s[2*t][3] - mn1);
            float p10 = ex2f(s[2*t+1][0] - mn0), p11 = ex2f(s[2*t+1][1] - mn0);
            float p12 = ex2f(s[2*t+1][2] - mn1), p13 = ex2f(s[2*t+1][3] - mn1);
            ls0 += (p00 + p01) + (p10 + p11);
            ls1 += (p02 + p03) + (p12 + p13);
            pAh[t][0] = cvt2_bf16(p00, p01);
            pAh[t][1] = cvt2_bf16(p02, p03);
            pAh[t][2] = cvt2_bf16(p10, p11);
            pAh[t][3] = cvt2_bf16(p12, p13);
            pAl[t][0] = cvt2_bf16(p00 - bf16_round(p00), p01 - bf16_round(p01));
            pAl[t][1] = cvt2_bf16(p02 - bf16_round(p02), p03 - bf16_round(p03));
            pAl[t][2] = cvt2_bf16(p10 - bf16_round(p10), p11 - bf16_round(p11));
            pAl[t][3] = cvt2_bf16(p12 - bf16_round(p12), p13 - bf16_round(p13));
        }
        l0 = l0 * fac0 + ls0;
        l1 = l1 * fac1 + ls1;
        m0 = mn0; m1 = mn1;
#pragma unroll
        for (int n = 0; n < 16; n++) {
            o[n][0] *= fac0; o[n][1] *= fac0;
            o[n][2] *= fac1; o[n][3] *= fac1;
        }

        // ---- O += P @ V ----
#pragma unroll
        for (int t = 0; t < 4; t++) {
#pragma unroll
            for (int h = 0; h < 2; h++) {
                unsigned vhr[4][4], vlr[4][4];
#pragma unroll
                for (int g4 = 0; g4 < 4; g4++) {
                    const int g = h * 4 + g4;
                    unsigned boff = (unsigned)((g * 16 + b_n_off) * FL_VROWB + (t * 16 + b_k_off) * 2);
                    ldsm_x4(vH + boff, vhr[g4][0], vhr[g4][1], vhr[g4][2], vhr[g4][3]);
                    ldsm_x4(vL + boff, vlr[g4][0], vlr[g4][1], vlr[g4][2], vlr[g4][3]);
                }
#pragma unroll
                for (int g4 = 0; g4 < 4; g4++) {
                    const int g = h * 4 + g4;
                    mma_bf16(o[2*g],   pAh[t], vhr[g4]);
                    mma_bf16(o[2*g+1], pAh[t], vhr[g4] + 2);
                }
#pragma unroll
                for (int g4 = 0; g4 < 4; g4++) {
                    const int g = h * 4 + g4;
                    mma_bf16(o[2*g],   pAh[t], vlr[g4]);
                    mma_bf16(o[2*g+1], pAh[t], vlr[g4] + 2);
                }
#pragma unroll
                for (int g4 = 0; g4 < 4; g4++) {
                    const int g = h * 4 + g4;
                    mma_bf16(o[2*g],   pAl[t], vhr[g4]);
                    mma_bf16(o[2*g+1], pAl[t], vhr[g4] + 2);
                }
            }
        }
    }

    // ---- epilogue ----
    l0 += __shfl_xor_sync(0xffffffffu, l0, 1);
    l0 += __shfl_xor_sync(0xffffffffu, l0, 2);
    l1 += __shfl_xor_sync(0xffffffffu, l1, 1);
    l1 += __shfl_xor_sync(0xffffffffu, l1, 2);

    const int r0 = wm * 16 + (lane >> 2);
    float* __restrict__ Og = g_O[sp] + (qrow0) * HEAD;
#pragma unroll
    for (int n = 0; n < 16; n++) {
        const int col = n * 8 + (lane & 3) * 2;
        *(float2*)&Og[(long)r0 * HEAD + col]       = make_float2(o[n][0], o[n][1]);
        *(float2*)&Og[(long)(r0 + 8) * HEAD + col] = make_float2(o[n][2], o[n][3]);
    }
    if ((lane & 3) == 0) {
        const long rowg = (long)b * SEQ + qt * 128 + r0;
        g_m[sp][rowg] = m0;     g_l[sp][rowg] = l0;
        g_m[sp][rowg + 8] = m1; g_l[sp][rowg + 8] = l1;
    }
}

// ---------------------------------------------------------------------------
// Combine 4 splits (base-2 weights), float4 vectorized.
// ---------------------------------------------------------------------------
__global__ __launch_bounds__(256) void combine_kernel(float* __restrict__ out)
{
    const int id = blockIdx.x * 256 + threadIdx.x;
    const long base = (long)id * 4;
    const int row = (int)(base >> 7);

    float mv[NSPLIT], lv[NSPLIT];
    float M = -1e30f;
#pragma unroll
    for (int s = 0; s < NSPLIT; s++) {
        mv[s] = g_m[s][row];
        lv[s] = g_l[s][row];
        M = fmaxf(M, mv[s]);
    }
    float4 num = make_float4(0.f, 0.f, 0.f, 0.f);
    float den = 0.f;
#pragma unroll
    for (int s = 0; s < NSPLIT; s++) {
        float w = ex2f(mv[s] - M);
        float4 ov = *(const float4*)&g_O[s][base];
        num.x += w * ov.x; num.y += w * ov.y;
        num.z += w * ov.z; num.w += w * ov.w;
        den += w * lv[s];
    }
    float inv = 1.0f / den;
    *(float4*)&out[base] = make_float4(num.x*inv, num.y*inv, num.z*inv, num.w*inv);
}

// ---------------------------------------------------------------------------
extern "C" void kernel_launch(void* const* d_in, const int* in_sizes, int n_in,
                              void* d_out, int out_size)
{
    const float* X  = (const float*)d_in[0];
    const float* WQ = (const float*)d_in[1];
    const float* WK = (const float*)d_in[2];
    const float* WV = (const float*)d_in[3];
    float* out = (float*)d_out;

    cudaFuncSetAttribute(proj_mma_kernel,
                         cudaFuncAttributeMaxDynamicSharedMemorySize, PJ_SMEM);
    cudaFuncSetAttribute(flash_kernel,
                         cudaFuncAttributeMaxDynamicSharedMemorySize, FL_SMEM);

    convert_x_kernel<<<(BATCH*SEQ*EMB)/1024, 256>>>(X);                  // 0
    convert_wv_kernel<<<(384*EMB)/1024, 256>>>(WQ, WK, WV);              // 1
    proj_mma_kernel<<<dim3(64, 2, 2), 256, PJ_SMEM>>>();                 // 2
    proj_reduce_kernel<<<(BATCH*SEQ*256/4)/256, 256>>>();                // 3
    flash_kernel<<<BATCH * 16 * NSPLIT, 256, FL_SMEM>>>();               // 4
    combine_kernel<<<(BATCH*SEQ*HEAD/4)/256, 256>>>(out);                // 5
}

// round 12
// speedup vs baseline: 1.2591x; 1.2453x over previous
#include <cuda_runtime.h>
#include <cuda_fp16.h>
#include <math.h>
#include <cstdint>

#define BATCH 4
#define SEQ   2048
#define EMB   2048
#define HEAD  128
#define NSPLIT 4

// ------------------------- device scratch -------------------------
__device__ __half g_Xhi[BATCH*SEQ*EMB];
__device__ __half g_Xlo[BATCH*SEQ*EMB];
__device__ __half g_Bh [256*EMB];        // rows 0-127: WQ, 128-255: WK (single fp16)
__device__ __half g_Vh [HEAD*EMB];       // W_V as-is [h][k] (single fp16)
__device__ __half g_Qhi[BATCH*SEQ*HEAD]; // pre-scaled by log2e/sqrt(128)
__device__ __half g_Qlo[BATCH*SEQ*HEAD];
__device__ __half g_Khi[BATCH*SEQ*HEAD];
__device__ __half g_Klo[BATCH*SEQ*HEAD];
__device__ float g_O[NSPLIT][BATCH*SEQ*HEAD];
__device__ float g_m[NSPLIT][BATCH*SEQ];     // base-2 domain
__device__ float g_l[NSPLIT][BATCH*SEQ];

// ------------------------- helpers -------------------------
__device__ __forceinline__ void cp16s(unsigned sd, const void* gsrc) {
    asm volatile("cp.async.cg.shared.global [%0], [%1], 16;\n" :: "r"(sd), "l"(gsrc));
}
#define CP_COMMIT() asm volatile("cp.async.commit_group;\n" ::: "memory")
#define CP_WAIT(N)  asm volatile("cp.async.wait_group %0;\n" :: "n"(N) : "memory")

__device__ __forceinline__ unsigned smem_u32(const void* p) {
    return (unsigned)__cvta_generic_to_shared((void*)p);
}
__device__ __forceinline__ void ldsm_x4(unsigned addr, unsigned& r0, unsigned& r1,
                                        unsigned& r2, unsigned& r3) {
    asm volatile("ldmatrix.sync.aligned.m8n8.x4.shared.b16 {%0,%1,%2,%3}, [%4];"
                 : "=r"(r0), "=r"(r1), "=r"(r2), "=r"(r3) : "r"(addr));
}
__device__ __forceinline__ void mma_f16(float* c, const unsigned* a, const unsigned* b) {
    asm volatile(
        "mma.sync.aligned.m16n8k16.row.col.f32.f16.f16.f32 "
        "{%0,%1,%2,%3}, {%4,%5,%6,%7}, {%8,%9}, {%0,%1,%2,%3};"
        : "+f"(c[0]), "+f"(c[1]), "+f"(c[2]), "+f"(c[3])
        : "r"(a[0]), "r"(a[1]), "r"(a[2]), "r"(a[3]), "r"(b[0]), "r"(b[1]));
}
// pack two f32 -> f16x2 (lo_val in low 16 bits)
__device__ __forceinline__ unsigned cvt2_f16(float lo_val, float hi_val) {
    unsigned r;
    asm("cvt.rn.f16x2.f32 %0, %1, %2;" : "=r"(r) : "f"(hi_val), "f"(lo_val));
    return r;
}
__device__ __forceinline__ float f16_round(float x) {
    return __half2float(__float2half_rn(x));
}
__device__ __forceinline__ float ex2f(float x) {
    float y; asm("ex2.approx.f32 %0, %1;" : "=f"(y) : "f"(x)); return y;
}

// ---------------------------------------------------------------------------
// convert X -> (hi, lo) fp16 split (exact to ~2^-22)
// ---------------------------------------------------------------------------
__global__ __launch_bounds__(256) void convert_x_kernel(const float* __restrict__ X)
{
    long i = ((long)blockIdx.x * 256 + threadIdx.x) * 4;
    float4 v = *(const float4*)(X + i);
    float vv[4] = {v.x, v.y, v.z, v.w};
    __half hi[4], lo[4];
#pragma unroll
    for (int q = 0; q < 4; q++) {
        hi[q] = __float2half_rn(vv[q]);
        lo[q] = __float2half_rn(vv[q] - __half2float(hi[q]));
    }
    *(ushort4*)&g_Xhi[i] = *(ushort4*)hi;
    *(ushort4*)&g_Xlo[i] = *(ushort4*)lo;
}

// ---------------------------------------------------------------------------
// convert WQ/WK -> g_Bh (single fp16), WV -> g_Vh (single fp16)
// ---------------------------------------------------------------------------
__global__ __launch_bounds__(256) void convert_wv_kernel(
    const float* __restrict__ WQ, const float* __restrict__ WK,
    const float* __restrict__ WV)
{
    long i = ((long)blockIdx.x * 256 + threadIdx.x) * 4;
    const float* src;
    __half* dst;
    long didx;
    if (i < 256L * EMB) {
        int r = (int)(i >> 11);
        long c = i & 2047;
        src = (r < 128) ? (WQ + (long)r * EMB + c) : (WK + (long)(r - 128) * EMB + c);
        dst = g_Bh; didx = i;
    } else {
        long j = i - 256L * EMB;
        src = WV + j;
        dst = g_Vh; didx = j;
    }
    float4 v = *(const float4*)src;
    __half h[4] = {__float2half_rn(v.x), __float2half_rn(v.y),
                   __float2half_rn(v.z), __float2half_rn(v.w)};
    *(ushort4*)&dst[didx] = *(ushort4*)h;
}

// ---------------------------------------------------------------------------
// mma.sync projection GEMM: Q/K(8192 x 128 each) = X @ B^T
// fp16, A=X split (exact), B=W single-rounded -> 2 MMAs per product.
// CTA 128x128 (grid 64 x 2), BK=64, double-buffered cp.async, 8 warps (4m x 2n)
// ---------------------------------------------------------------------------
#define PJ_ROWB  144                  // 64 fp16 = 128 B data + 16 B pad
#define PJ_ARR   (128*PJ_ROWB)        // 18432 B per tile array
#define PJ_BUF   (3*PJ_ARR)           // A_hi A_lo B = 55296 B
#define PJ_SMEM  (2*PJ_BUF)           // 110592 B

__global__ __launch_bounds__(256) void proj_mma_kernel()
{
    extern __shared__ unsigned char dsm8[];
    const unsigned sb = smem_u32(dsm8);

    const int tid = threadIdx.x;
    const int wid = tid >> 5;
    const int lane = tid & 31;
    const int wm = wid & 3;
    const int wn = wid >> 2;

    const int m0 = blockIdx.x * 128;
    const int nt = blockIdx.y;     // 0 -> Q, 1 -> K

    float acc[2][8][4];
#pragma unroll
    for (int m = 0; m < 2; m++)
#pragma unroll
        for (int n = 0; n < 8; n++)
#pragma unroll
            for (int q = 0; q < 4; q++) acc[m][n][q] = 0.f;

    auto load_tile = [&](int buf, int kt) {
        const unsigned base = sb + buf * PJ_BUF;
        const long kof = (long)kt * 64;
        for (int c = tid; c < 1024; c += 256) {
            int r = c >> 3, ch = c & 7;
            unsigned so = (unsigned)(r * PJ_ROWB + ch * 16);
            const long gix = (long)(m0 + r) * EMB + kof + ch * 8;
            cp16s(base + so,          g_Xhi + gix);
            cp16s(base + PJ_ARR + so, g_Xlo + gix);
        }
        for (int c = tid; c < 1024; c += 256) {
            int r = c >> 3, ch = c & 7;
            unsigned so = (unsigned)(r * PJ_ROWB + ch * 16);
            const long gix = (long)(nt * 128 + r) * EMB + kof + ch * 8;
            cp16s(base + 2*PJ_ARR + so, g_Bh + gix);
        }
        CP_COMMIT();
    };

    load_tile(0, 0);

    const int a_row_off = (lane & 7) + ((lane >> 3) & 1) * 8;
    const int a_kb_off  = (lane >> 4) * 8;
    const int b_n_off   = (lane & 7) + ((lane >> 3) >> 1) * 8;
    const int b_k_off   = ((lane >> 3) & 1) * 8;

    for (int kt = 0; kt < 32; kt++) {
        const int buf = kt & 1;
        __syncthreads();

        if (kt + 1 < 32) {
            load_tile(buf ^ 1, kt + 1);
            CP_WAIT(1);
        } else {
            CP_WAIT(0);
        }
        __syncthreads();

        const unsigned aH = sb + buf * PJ_BUF;
        const unsigned aL = aH + PJ_ARR;
        const unsigned bB = aH + 2*PJ_ARR;

#pragma unroll
        for (int kf = 0; kf < 4; kf++) {
            const int kb = kf * 16;
            unsigned ah[2][4], al[2][4];
#pragma unroll
            for (int m = 0; m < 2; m++) {
                unsigned row = (unsigned)(wm * 32 + m * 16 + a_row_off);
                unsigned off = row * PJ_ROWB + (unsigned)(kb + a_kb_off) * 2;
                ldsm_x4(aH + off, ah[m][0], ah[m][1], ah[m][2], ah[m][3]);
                ldsm_x4(aL + off, al[m][0], al[m][1], al[m][2], al[m][3]);
            }
            unsigned bb[8][2];
#pragma unroll
            for (int g = 0; g < 4; g++) {
                unsigned nrow = (unsigned)(wn * 64 + g * 16 + b_n_off);
                unsigned off = nrow * PJ_ROWB + (unsigned)(kb + b_k_off) * 2;
                ldsm_x4(bB + off, bb[g*2][0], bb[g*2][1], bb[g*2+1][0], bb[g*2+1][1]);
            }
#pragma unroll
            for (int m = 0; m < 2; m++)
#pragma unroll
                for (int n = 0; n < 8; n++) mma_f16(acc[m][n], ah[m], bb[n]);
#pragma unroll
            for (int m = 0; m < 2; m++)
#pragma unroll
                for (int n = 0; n < 8; n++) mma_f16(acc[m][n], al[m], bb[n]);
        }
    }

    // ---- epilogue: write fp16 hi/lo (Q pre-scaled by log2e/sqrt(128)) ----
    __half* __restrict__ dhi = nt ? g_Khi : g_Qhi;
    __half* __restrict__ dlo = nt ? g_Klo : g_Qlo;
    const float scl = nt ? 1.0f : (0.08838834764831845f * 1.4426950408889634f);
#pragma unroll
    for (int m = 0; m < 2; m++) {
        const int row = m0 + wm * 32 + m * 16 + (lane >> 2);
#pragma unroll
        for (int n = 0; n < 8; n++) {
            const int col = wn * 64 + n * 8 + (lane & 3) * 2;
            float v0 = acc[m][n][0] * scl, v1 = acc[m][n][1] * scl;
            float v2 = acc[m][n][2] * scl, v3 = acc[m][n][3] * scl;
            *(unsigned*)&dhi[(long)row * HEAD + col] = cvt2_f16(v0, v1);
            *(unsigned*)&dlo[(long)row * HEAD + col] =
                cvt2_f16(v0 - f16_round(v0), v1 - f16_round(v1));
            *(unsigned*)&dhi[(long)(row + 8) * HEAD + col] = cvt2_f16(v2, v3);
            *(unsigned*)&dlo[(long)(row + 8) * HEAD + col] =
                cvt2_f16(v2 - f16_round(v2), v3 - f16_round(v3));
        }
    }
}

// ---------------------------------------------------------------------------
// Tensor-core causal flash attention, fp16, split-K(4).
// S: 3-term (Q,K hi/lo exact).  PV: P split (exact) x V single -> 2 terms.
// ---------------------------------------------------------------------------
#define FL_QROWB 272
#define FL_KROWB 272
#define FL_VROWB 144
#define FL_QH 0
#define FL_QL 34816
#define FL_KB 69632                   // 2 bufs x {KH 17408, KL 17408}
#define FL_VB 139264                  // 2 bufs x 18432 (single V)
#define FL_SMEM 176128

__global__ __launch_bounds__(256) void flash_kernel()
{
    extern __shared__ unsigned char dsm8[];
    const unsigned sb = smem_u32(dsm8);

    const int tid = threadIdx.x;
    const int wm  = tid >> 5;
    const int lane = tid & 31;

    const int bid = blockIdx.x;
    const int qt = 15 - (bid >> 4);
    const int b  = (bid >> 2) & 3;
    const int sp = bid & 3;

    const int nkt   = 2 * (qt + 1);
    const int chunk = (nkt + NSPLIT - 1) / NSPLIT;
    const int kt_lo = sp * chunk;
    const int kt_hi = min(nkt, kt_lo + chunk);

    const long qrow0 = (long)b * SEQ + qt * 128;

    for (int c = tid; c < 2048; c += 256) {
        int r = c >> 4, ch = c & 15;
        unsigned so = (unsigned)(r * FL_QROWB + ch * 16);
        const long gix = (qrow0 + r) * HEAD + ch * 8;
        cp16s(sb + FL_QH + so, g_Qhi + gix);
        cp16s(sb + FL_QL + so, g_Qlo + gix);
    }

    auto load_kv = [&](int buf, int kt) {
        const unsigned kh = sb + FL_KB + buf * 34816;
        const unsigned vh = sb + FL_VB + buf * 18432;
        for (int c = tid; c < 1024; c += 256) {
            int r = c >> 4, ch = c & 15;
            unsigned so = (unsigned)(r * FL_KROWB + ch * 16);
            const long gix = ((long)b * SEQ + kt * 64 + r) * HEAD + ch * 8;
            cp16s(kh + so,         g_Khi + gix);
            cp16s(kh + 17408 + so, g_Klo + gix);
        }
        for (int c = tid; c < 1024; c += 256) {
            int r = c >> 3, ch = c & 7;
            unsigned so = (unsigned)(r * FL_VROWB + ch * 16);
            const long gix = (long)r * EMB + kt * 64 + ch * 8;
            cp16s(vh + so, g_Vh + gix);
        }
        CP_COMMIT();
    };

    if (kt_lo < kt_hi) load_kv(0, kt_lo);
    else CP_COMMIT();

    float o[16][4];
#pragma unroll
    for (int n = 0; n < 16; n++)
#pragma unroll
        for (int q = 0; q < 4; q++) o[n][q] = 0.f;
    float m0 = -1e30f, m1 = -1e30f;
    float l0 = 0.f, l1 = 0.f;

    const int a_row_off = (lane & 7) + ((lane >> 3) & 1) * 8;
    const int a_kb_off  = (lane >> 4) * 8;
    const int b_n_off   = (lane & 7) + ((lane >> 3) >> 1) * 8;
    const int b_k_off   = ((lane >> 3) & 1) * 8;

    for (int kt = kt_lo; kt < kt_hi; kt++) {
        const int buf = (kt - kt_lo) & 1;
        __syncthreads();

        if (kt + 1 < kt_hi) {
            load_kv(buf ^ 1, kt + 1);
            CP_WAIT(1);
        } else {
            CP_WAIT(0);
        }
        __syncthreads();

        const unsigned kH = sb + FL_KB + buf * 34816;
        const unsigned kL = kH + 17408;
        const unsigned vB = sb + FL_VB + buf * 18432;

        // ---- S = Q K^T, 3-term fp16 (exact to ~2^-22) ----
        float s[8][4];
#pragma unroll
        for (int n = 0; n < 8; n++)
#pragma unroll
            for (int q = 0; q < 4; q++) s[n][q] = 0.f;

#pragma unroll
        for (int t = 0; t < 8; t++) {
            const int kb = t * 16;
            unsigned aoff = (unsigned)((wm * 16 + a_row_off) * FL_QROWB + (kb + a_kb_off) * 2);
            unsigned ah[4], al[4];
            ldsm_x4(sb + FL_QH + aoff, ah[0], ah[1], ah[2], ah[3]);
            ldsm_x4(sb + FL_QL + aoff, al[0], al[1], al[2], al[3]);
            unsigned bh[4][4], bl[4][4];
#pragma unroll
            for (int g = 0; g < 4; g++) {
                unsigned boff = (unsigned)((g * 16 + b_n_off) * FL_KROWB + (kb + b_k_off) * 2);
                ldsm_x4(kH + boff, bh[g][0], bh[g][1], bh[g][2], bh[g][3]);
                ldsm_x4(kL + boff, bl[g][0], bl[g][1], bl[g][2], bl[g][3]);
            }
#pragma unroll
            for (int g = 0; g < 4; g++) {
                mma_f16(s[2*g],   ah, bh[g]);
                mma_f16(s[2*g+1], ah, bh[g] + 2);
            }
#pragma unroll
            for (int g = 0; g < 4; g++) {
                mma_f16(s[2*g],   ah, bl[g]);
                mma_f16(s[2*g+1], ah, bl[g] + 2);
            }
#pragma unroll
            for (int g = 0; g < 4; g++) {
                mma_f16(s[2*g],   al, bh[g]);
                mma_f16(s[2*g+1], al, bh[g] + 2);
            }
        }

        // ---- causal mask ----
        const int qr0 = qt * 128 + wm * 16 + (lane >> 2);
        const int qr1 = qr0 + 8;
        if (kt * 64 + 63 > qt * 128 + wm * 16) {
#pragma unroll
            for (int n = 0; n < 8; n++) {
                int c0 = kt * 64 + n * 8 + (lane & 3) * 2;
                if (c0     > qr0) s[n][0] = -1e30f;
                if (c0 + 1 > qr0) s[n][1] = -1e30f;
                if (c0     > qr1) s[n][2] = -1e30f;
                if (c0 + 1 > qr1) s[n][3] = -1e30f;
            }
        }

        // ---- online softmax (base-2 domain) ----
        float mx0 = -1e30f, mx1 = -1e30f;
#pragma unroll
        for (int n = 0; n < 8; n++) {
            mx0 = fmaxf(mx0, fmaxf(s[n][0], s[n][1]));
            mx1 = fmaxf(mx1, fmaxf(s[n][2], s[n][3]));
        }
        mx0 = fmaxf(mx0, __shfl_xor_sync(0xffffffffu, mx0, 1));
        mx0 = fmaxf(mx0, __shfl_xor_sync(0xffffffffu, mx0, 2));
        mx1 = fmaxf(mx1, __shfl_xor_sync(0xffffffffu, mx1, 1));
        mx1 = fmaxf(mx1, __shfl_xor_sync(0xffffffffu, mx1, 2));

        const float mn0 = fmaxf(m0, mx0);
        const float mn1 = fmaxf(m1, mx1);
        const float fac0 = ex2f(m0 - mn0);
        const float fac1 = ex2f(m1 - mn1);

        unsigned pAh[4][4], pAl[4][4];
        float ls0 = 0.f, ls1 = 0.f;
#pragma unroll
        for (int t = 0; t < 4; t++) {
            float p00 = ex2f(s[2*t][0] - mn0),   p01 = ex2f(s[2*t][1] - mn0);
            float p02 = ex2f(s[2*t][2] - mn1),   p03 = ex2f(s[2*t][3] - mn1);
            float p10 = ex2f(s[2*t+1][0] - mn0), p11 = ex2f(s[2*t+1][1] - mn0);
            float p12 = ex2f(s[2*t+1][2] - mn1), p13 = ex2f(s[2*t+1][3] - mn1);
            ls0 += (p00 + p01) + (p10 + p11);
            ls1 += (p02 + p03) + (p12 + p13);
            pAh[t][0] = cvt2_f16(p00, p01);
            pAh[t][1] = cvt2_f16(p02, p03);
            pAh[t][2] = cvt2_f16(p10, p11);
            pAh[t][3] = cvt2_f16(p12, p13);
            pAl[t][0] = cvt2_f16(p00 - f16_round(p00), p01 - f16_round(p01));
            pAl[t][1] = cvt2_f16(p02 - f16_round(p02), p03 - f16_round(p03));
            pAl[t][2] = cvt2_f16(p10 - f16_round(p10), p11 - f16_round(p11));
            pAl[t][3] = cvt2_f16(p12 - f16_round(p12), p13 - f16_round(p13));
        }
        l0 = l0 * fac0 + ls0;
        l1 = l1 * fac1 + ls1;
        m0 = mn0; m1 = mn1;
#pragma unroll
        for (int n = 0; n < 16; n++) {
            o[n][0] *= fac0; o[n][1] *= fac0;
            o[n][2] *= fac1; o[n][3] *= fac1;
        }

        // ---- O += P @ V : P split (exact), V single -> 2 terms ----
#pragma unroll
        for (int t = 0; t < 4; t++) {
#pragma unroll
            for (int h = 0; h < 2; h++) {
                unsigned vr[4][4];
#pragma unroll
                for (int g4 = 0; g4 < 4; g4++) {
                    const int g = h * 4 + g4;
                    unsigned boff = (unsigned)((g * 16 + b_n_off) * FL_VROWB + (t * 16 + b_k_off) * 2);
                    ldsm_x4(vB + boff, vr[g4][0], vr[g4][1], vr[g4][2], vr[g4][3]);
                }
#pragma unroll
                for (int g4 = 0; g4 < 4; g4++) {
                    const int g = h * 4 + g4;
                    mma_f16(o[2*g],   pAh[t], vr[g4]);
                    mma_f16(o[2*g+1], pAh[t], vr[g4] + 2);
                }
#pragma unroll
                for (int g4 = 0; g4 < 4; g4++) {
                    const int g = h * 4 + g4;
                    mma_f16(o[2*g],   pAl[t], vr[g4]);
                    mma_f16(o[2*g+1], pAl[t], vr[g4] + 2);
                }
            }
        }
    }

    // ---- epilogue ----
    l0 += __shfl_xor_sync(0xffffffffu, l0, 1);
    l0 += __shfl_xor_sync(0xffffffffu, l0, 2);
    l1 += __shfl_xor_sync(0xffffffffu, l1, 1);
    l1 += __shfl_xor_sync(0xffffffffu, l1, 2);

    const int r0 = wm * 16 + (lane >> 2);
    float* __restrict__ Og = g_O[sp] + (qrow0) * HEAD;
#pragma unroll
    for (int n = 0; n < 16; n++) {
        const int col = n * 8 + (lane & 3) * 2;
        *(float2*)&Og[(long)r0 * HEAD + col]       = make_float2(o[n][0], o[n][1]);
        *(float2*)&Og[(long)(r0 + 8) * HEAD + col] = make_float2(o[n][2], o[n][3]);
    }
    if ((lane & 3) == 0) {
        const long rowg = (long)b * SEQ + qt * 128 + r0;
        g_m[sp][rowg] = m0;     g_l[sp][rowg] = l0;
        g_m[sp][rowg + 8] = m1; g_l[sp][rowg + 8] = l1;
    }
}

// ---------------------------------------------------------------------------
// Combine 4 splits (base-2 weights), float4 vectorized.
// ---------------------------------------------------------------------------
__global__ __launch_bounds__(256) void combine_kernel(float* __restrict__ out)
{
    const int id = blockIdx.x * 256 + threadIdx.x;
    const long base = (long)id * 4;
    const int row = (int)(base >> 7);

    float mv[NSPLIT], lv[NSPLIT];
    float M = -1e30f;
#pragma unroll
    for (int s = 0; s < NSPLIT; s++) {
        mv[s] = g_m[s][row];
        lv[s] = g_l[s][row];
        M = fmaxf(M, mv[s]);
    }
    float4 num = make_float4(0.f, 0.f, 0.f, 0.f);
    float den = 0.f;
#pragma unroll
    for (int s = 0; s < NSPLIT; s++) {
        float w = ex2f(mv[s] - M);
        float4 ov = *(const float4*)&g_O[s][base];
        num.x += w * ov.x; num.y += w * ov.y;
        num.z += w * ov.z; num.w += w * ov.w;
        den += w * lv[s];
    }
    float inv = 1.0f / den;
    *(float4*)&out[base] = make_float4(num.x*inv, num.y*inv, num.z*inv, num.w*inv);
}

// ---------------------------------------------------------------------------
extern "C" void kernel_launch(void* const* d_in, const int* in_sizes, int n_in,
                              void* d_out, int out_size)
{
    const float* X  = (const float*)d_in[0];
    const float* WQ = (const float*)d_in[1];
    const float* WK = (const float*)d_in[2];
    const float* WV = (const float*)d_in[3];
    float* out = (float*)d_out;

    cudaFuncSetAttribute(proj_mma_kernel,
                         cudaFuncAttributeMaxDynamicSharedMemorySize, PJ_SMEM);
    cudaFuncSetAttribute(flash_kernel,
                         cudaFuncAttributeMaxDynamicSharedMemorySize, FL_SMEM);

    convert_x_kernel<<<(BATCH*SEQ*EMB)/1024, 256>>>(X);                  // 0
    convert_wv_kernel<<<(384*EMB)/1024, 256>>>(WQ, WK, WV);              // 1
    proj_mma_kernel<<<dim3(64, 2), 256, PJ_SMEM>>>();                    // 2
    flash_kernel<<<BATCH * 16 * NSPLIT, 256, FL_SMEM>>>();               // 3
    combine_kernel<<<(BATCH*SEQ*HEAD/4)/256, 256>>>(out);                // 4
}

// round 13
// speedup vs baseline: 1.6671x; 1.3241x over previous
#include <cuda_runtime.h>
#include <cuda_fp16.h>
#include <math.h>
#include <cstdint>

#define BATCH 4
#define SEQ   2048
#define EMB   2048
#define HEAD  128
#define NSPLIT 4

// ------------------------- device scratch -------------------------
__device__ __half g_Xh [BATCH*SEQ*EMB];  // X single fp16
__device__ __half g_Bh [256*EMB];        // rows 0-127: WQ, 128-255: WK (single fp16)
__device__ __half g_Vh [HEAD*EMB];       // W_V as-is [h][k] (single fp16)
__device__ __half g_Qhi[BATCH*SEQ*HEAD]; // pre-scaled by log2e/sqrt(128)
__device__ __half g_Qlo[BATCH*SEQ*HEAD];
__device__ __half g_Khi[BATCH*SEQ*HEAD];
__device__ __half g_Klo[BATCH*SEQ*HEAD];
__device__ float g_O[NSPLIT][BATCH*SEQ*HEAD];
__device__ float g_m[NSPLIT][BATCH*SEQ];     // base-2 domain
__device__ float g_l[NSPLIT][BATCH*SEQ];

// ------------------------- helpers -------------------------
__device__ __forceinline__ void cp16s(unsigned sd, const void* gsrc) {
    asm volatile("cp.async.cg.shared.global [%0], [%1], 16;\n" :: "r"(sd), "l"(gsrc));
}
#define CP_COMMIT() asm volatile("cp.async.commit_group;\n" ::: "memory")
#define CP_WAIT(N)  asm volatile("cp.async.wait_group %0;\n" :: "n"(N) : "memory")

__device__ __forceinline__ unsigned smem_u32(const void* p) {
    return (unsigned)__cvta_generic_to_shared((void*)p);
}
__device__ __forceinline__ void ldsm_x4(unsigned addr, unsigned& r0, unsigned& r1,
                                        unsigned& r2, unsigned& r3) {
    asm volatile("ldmatrix.sync.aligned.m8n8.x4.shared.b16 {%0,%1,%2,%3}, [%4];"
                 : "=r"(r0), "=r"(r1), "=r"(r2), "=r"(r3) : "r"(addr));
}
__device__ __forceinline__ void mma_f16(float* c, const unsigned* a, const unsigned* b) {
    asm volatile(
        "mma.sync.aligned.m16n8k16.row.col.f32.f16.f16.f32 "
        "{%0,%1,%2,%3}, {%4,%5,%6,%7}, {%8,%9}, {%0,%1,%2,%3};"
        : "+f"(c[0]), "+f"(c[1]), "+f"(c[2]), "+f"(c[3])
        : "r"(a[0]), "r"(a[1]), "r"(a[2]), "r"(a[3]), "r"(b[0]), "r"(b[1]));
}
__device__ __forceinline__ unsigned cvt2_f16(float lo_val, float hi_val) {
    unsigned r;
    asm("cvt.rn.f16x2.f32 %0, %1, %2;" : "=r"(r) : "f"(hi_val), "f"(lo_val));
    return r;
}
__device__ __forceinline__ float f16_round(float x) {
    return __half2float(__float2half_rn(x));
}
__device__ __forceinline__ float ex2f(float x) {
    float y; asm("ex2.approx.f32 %0, %1;" : "=f"(y) : "f"(x)); return y;
}

// ---------------------------------------------------------------------------
// convert X -> single fp16
// ---------------------------------------------------------------------------
__global__ __launch_bounds__(256) void convert_x_kernel(const float* __restrict__ X)
{
    long i = ((long)blockIdx.x * 256 + threadIdx.x) * 4;
    float4 v = *(const float4*)(X + i);
    __half h[4] = {__float2half_rn(v.x), __float2half_rn(v.y),
                   __float2half_rn(v.z), __float2half_rn(v.w)};
    *(ushort4*)&g_Xh[i] = *(ushort4*)h;
}

// ---------------------------------------------------------------------------
// convert WQ/WK -> g_Bh, WV -> g_Vh (single fp16)
// ---------------------------------------------------------------------------
__global__ __launch_bounds__(256) void convert_wv_kernel(
    const float* __restrict__ WQ, const float* __restrict__ WK,
    const float* __restrict__ WV)
{
    long i = ((long)blockIdx.x * 256 + threadIdx.x) * 4;
    const float* src;
    __half* dst;
    long didx;
    if (i < 256L * EMB) {
        int r = (int)(i >> 11);
        long c = i & 2047;
        src = (r < 128) ? (WQ + (long)r * EMB + c) : (WK + (long)(r - 128) * EMB + c);
        dst = g_Bh; didx = i;
    } else {
        long j = i - 256L * EMB;
        src = WV + j;
        dst = g_Vh; didx = j;
    }
    float4 v = *(const float4*)src;
    __half h[4] = {__float2half_rn(v.x), __float2half_rn(v.y),
                   __float2half_rn(v.z), __float2half_rn(v.w)};
    *(ushort4*)&dst[didx] = *(ushort4*)h;
}

// ---------------------------------------------------------------------------
// mma.sync projection GEMM: Q/K(8192 x 128 each) = X @ B^T
// Single fp16 both operands -> 1 MMA per product.
// CTA 128x128 (grid 64 x 2), BK=64, double-buffered cp.async, 8 warps (4m x 2n)
// ---------------------------------------------------------------------------
#define PJ_ROWB  144                  // 64 fp16 = 128 B data + 16 B pad
#define PJ_ARR   (128*PJ_ROWB)        // 18432 B per tile array
#define PJ_BUF   (2*PJ_ARR)           // A, B = 36864 B
#define PJ_SMEM  (2*PJ_BUF)           // 73728 B

__global__ __launch_bounds__(256) void proj_mma_kernel()
{
    extern __shared__ unsigned char dsm8[];
    const unsigned sb = smem_u32(dsm8);

    const int tid = threadIdx.x;
    const int wid = tid >> 5;
    const int lane = tid & 31;
    const int wm = wid & 3;
    const int wn = wid >> 2;

    const int m0 = blockIdx.x * 128;
    const int nt = blockIdx.y;     // 0 -> Q, 1 -> K

    float acc[2][8][4];
#pragma unroll
    for (int m = 0; m < 2; m++)
#pragma unroll
        for (int n = 0; n < 8; n++)
#pragma unroll
            for (int q = 0; q < 4; q++) acc[m][n][q] = 0.f;

    auto load_tile = [&](int buf, int kt) {
        const unsigned base = sb + buf * PJ_BUF;
        const long kof = (long)kt * 64;
        for (int c = tid; c < 1024; c += 256) {
            int r = c >> 3, ch = c & 7;
            unsigned so = (unsigned)(r * PJ_ROWB + ch * 16);
            cp16s(base + so, g_Xh + (long)(m0 + r) * EMB + kof + ch * 8);
        }
        for (int c = tid; c < 1024; c += 256) {
            int r = c >> 3, ch = c & 7;
            unsigned so = (unsigned)(r * PJ_ROWB + ch * 16);
            cp16s(base + PJ_ARR + so, g_Bh + (long)(nt * 128 + r) * EMB + kof + ch * 8);
        }
        CP_COMMIT();
    };

    load_tile(0, 0);

    const int a_row_off = (lane & 7) + ((lane >> 3) & 1) * 8;
    const int a_kb_off  = (lane >> 4) * 8;
    const int b_n_off   = (lane & 7) + ((lane >> 3) >> 1) * 8;
    const int b_k_off   = ((lane >> 3) & 1) * 8;

    for (int kt = 0; kt < 32; kt++) {
        const int buf = kt & 1;
        __syncthreads();

        if (kt + 1 < 32) {
            load_tile(buf ^ 1, kt + 1);
            CP_WAIT(1);
        } else {
            CP_WAIT(0);
        }
        __syncthreads();

        const unsigned aA = sb + buf * PJ_BUF;
        const unsigned bB = aA + PJ_ARR;

#pragma unroll
        for (int kf = 0; kf < 4; kf++) {
            const int kb = kf * 16;
            unsigned aa[2][4];
#pragma unroll
            for (int m = 0; m < 2; m++) {
                unsigned row = (unsigned)(wm * 32 + m * 16 + a_row_off);
                unsigned off = row * PJ_ROWB + (unsigned)(kb + a_kb_off) * 2;
                ldsm_x4(aA + off, aa[m][0], aa[m][1], aa[m][2], aa[m][3]);
            }
            unsigned bb[8][2];
#pragma unroll
            for (int g = 0; g < 4; g++) {
                unsigned nrow = (unsigned)(wn * 64 + g * 16 + b_n_off);
                unsigned off = nrow * PJ_ROWB + (unsigned)(kb + b_k_off) * 2;
                ldsm_x4(bB + off, bb[g*2][0], bb[g*2][1], bb[g*2+1][0], bb[g*2+1][1]);
            }
#pragma unroll
            for (int m = 0; m < 2; m++)
#pragma unroll
                for (int n = 0; n < 8; n++) mma_f16(acc[m][n], aa[m], bb[n]);
        }
    }

    // ---- epilogue: write fp16 hi/lo (Q pre-scaled by log2e/sqrt(128)) ----
    __half* __restrict__ dhi = nt ? g_Khi : g_Qhi;
    __half* __restrict__ dlo = nt ? g_Klo : g_Qlo;
    const float scl = nt ? 1.0f : (0.08838834764831845f * 1.4426950408889634f);
#pragma unroll
    for (int m = 0; m < 2; m++) {
        const int row = m0 + wm * 32 + m * 16 + (lane >> 2);
#pragma unroll
        for (int n = 0; n < 8; n++) {
            const int col = wn * 64 + n * 8 + (lane & 3) * 2;
            float v0 = acc[m][n][0] * scl, v1 = acc[m][n][1] * scl;
            float v2 = acc[m][n][2] * scl, v3 = acc[m][n][3] * scl;
            *(unsigned*)&dhi[(long)row * HEAD + col] = cvt2_f16(v0, v1);
            *(unsigned*)&dlo[(long)row * HEAD + col] =
                cvt2_f16(v0 - f16_round(v0), v1 - f16_round(v1));
            *(unsigned*)&dhi[(long)(row + 8) * HEAD + col] = cvt2_f16(v2, v3);
            *(unsigned*)&dlo[(long)(row + 8) * HEAD + col] =
                cvt2_f16(v2 - f16_round(v2), v3 - f16_round(v3));
        }
    }
}

// ---------------------------------------------------------------------------
// Tensor-core causal flash attention, fp16, split-K(4).
// S: 3-term (Q,K hi/lo exact).  PV: P single x V single -> 1 term.
// ---------------------------------------------------------------------------
#define FL_QROWB 272
#define FL_KROWB 272
#define FL_VROWB 144
#define FL_QH 0
#define FL_QL 34816
#define FL_KB 69632                   // 2 bufs x {KH 17408, KL 17408}
#define FL_VB 139264                  // 2 bufs x 18432 (single V)
#define FL_SMEM 176128

__global__ __launch_bounds__(256) void flash_kernel()
{
    extern __shared__ unsigned char dsm8[];
    const unsigned sb = smem_u32(dsm8);

    const int tid = threadIdx.x;
    const int wm  = tid >> 5;
    const int lane = tid & 31;

    const int bid = blockIdx.x;
    const int qt = 15 - (bid >> 4);
    const int b  = (bid >> 2) & 3;
    const int sp = bid & 3;

    const int nkt   = 2 * (qt + 1);
    const int chunk = (nkt + NSPLIT - 1) / NSPLIT;
    const int kt_lo = sp * chunk;
    const int kt_hi = min(nkt, kt_lo + chunk);

    const long qrow0 = (long)b * SEQ + qt * 128;

    for (int c = tid; c < 2048; c += 256) {
        int r = c >> 4, ch = c & 15;
        unsigned so = (unsigned)(r * FL_QROWB + ch * 16);
        const long gix = (qrow0 + r) * HEAD + ch * 8;
        cp16s(sb + FL_QH + so, g_Qhi + gix);
        cp16s(sb + FL_QL + so, g_Qlo + gix);
    }

    auto load_kv = [&](int buf, int kt) {
        const unsigned kh = sb + FL_KB + buf * 34816;
        const unsigned vh = sb + FL_VB + buf * 18432;
        for (int c = tid; c < 1024; c += 256) {
            int r = c >> 4, ch = c & 15;
            unsigned so = (unsigned)(r * FL_KROWB + ch * 16);
            const long gix = ((long)b * SEQ + kt * 64 + r) * HEAD + ch * 8;
            cp16s(kh + so,         g_Khi + gix);
            cp16s(kh + 17408 + so, g_Klo + gix);
        }
        for (int c = tid; c < 1024; c += 256) {
            int r = c >> 3, ch = c & 7;
            unsigned so = (unsigned)(r * FL_VROWB + ch * 16);
            cp16s(vh + so, g_Vh + (long)r * EMB + kt * 64 + ch * 8);
        }
        CP_COMMIT();
    };

    if (kt_lo < kt_hi) load_kv(0, kt_lo);
    else CP_COMMIT();

    float o[16][4];
#pragma unroll
    for (int n = 0; n < 16; n++)
#pragma unroll
        for (int q = 0; q < 4; q++) o[n][q] = 0.f;
    float m0 = -1e30f, m1 = -1e30f;
    float l0 = 0.f, l1 = 0.f;

    const int a_row_off = (lane & 7) + ((lane >> 3) & 1) * 8;
    const int a_kb_off  = (lane >> 4) * 8;
    const int b_n_off   = (lane & 7) + ((lane >> 3) >> 1) * 8;
    const int b_k_off   = ((lane >> 3) & 1) * 8;

    for (int kt = kt_lo; kt < kt_hi; kt++) {
        const int buf = (kt - kt_lo) & 1;
        __syncthreads();

        if (kt + 1 < kt_hi) {
            load_kv(buf ^ 1, kt + 1);
            CP_WAIT(1);
        } else {
            CP_WAIT(0);
        }
        __syncthreads();

        const unsigned kH = sb + FL_KB + buf * 34816;
        const unsigned kL = kH + 17408;
        const unsigned vB = sb + FL_VB + buf * 18432;

        // ---- S = Q K^T, 3-term fp16 (Q,K hi/lo exact) ----
        float s[8][4];
#pragma unroll
        for (int n = 0; n < 8; n++)
#pragma unroll
            for (int q = 0; q < 4; q++) s[n][q] = 0.f;

#pragma unroll
        for (int t = 0; t < 8; t++) {
            const int kb = t * 16;
            unsigned aoff = (unsigned)((wm * 16 + a_row_off) * FL_QROWB + (kb + a_kb_off) * 2);
            unsigned ah[4], al[4];
            ldsm_x4(sb + FL_QH + aoff, ah[0], ah[1], ah[2], ah[3]);
            ldsm_x4(sb + FL_QL + aoff, al[0], al[1], al[2], al[3]);
            unsigned bh[4][4], bl[4][4];
#pragma unroll
            for (int g = 0; g < 4; g++) {
                unsigned boff = (unsigned)((g * 16 + b_n_off) * FL_KROWB + (kb + b_k_off) * 2);
                ldsm_x4(kH + boff, bh[g][0], bh[g][1], bh[g][2], bh[g][3]);
                ldsm_x4(kL + boff, bl[g][0], bl[g][1], bl[g][2], bl[g][3]);
            }
#pragma unroll
            for (int g = 0; g < 4; g++) {
                mma_f16(s[2*g],   ah, bh[g]);
                mma_f16(s[2*g+1], ah, bh[g] + 2);
            }
#pragma unroll
            for (int g = 0; g < 4; g++) {
                mma_f16(s[2*g],   ah, bl[g]);
                mma_f16(s[2*g+1], ah, bl[g] + 2);
            }
#pragma unroll
            for (int g = 0; g < 4; g++) {
                mma_f16(s[2*g],   al, bh[g]);
                mma_f16(s[2*g+1], al, bh[g] + 2);
            }
        }

        // ---- causal mask ----
        const int qr0 = qt * 128 + wm * 16 + (lane >> 2);
        const int qr1 = qr0 + 8;
        if (kt * 64 + 63 > qt * 128 + wm * 16) {
#pragma unroll
            for (int n = 0; n < 8; n++) {
                int c0 = kt * 64 + n * 8 + (lane & 3) * 2;
                if (c0     > qr0) s[n][0] = -1e30f;
                if (c0 + 1 > qr0) s[n][1] = -1e30f;
                if (c0     > qr1) s[n][2] = -1e30f;
                if (c0 + 1 > qr1) s[n][3] = -1e30f;
            }
        }

        // ---- online softmax (base-2 domain) ----
        float mx0 = -1e30f, mx1 = -1e30f;
#pragma unroll
        for (int n = 0; n < 8; n++) {
            mx0 = fmaxf(mx0, fmaxf(s[n][0], s[n][1]));
            mx1 = fmaxf(mx1, fmaxf(s[n][2], s[n][3]));
        }
        mx0 = fmaxf(mx0, __shfl_xor_sync(0xffffffffu, mx0, 1));
        mx0 = fmaxf(mx0, __shfl_xor_sync(0xffffffffu, mx0, 2));
        mx1 = fmaxf(mx1, __shfl_xor_sync(0xffffffffu, mx1, 1));
        mx1 = fmaxf(mx1, __shfl_xor_sync(0xffffffffu, mx1, 2));

        const float mn0 = fmaxf(m0, mx0);
        const float mn1 = fmaxf(m1, mx1);
        const float fac0 = ex2f(m0 - mn0);
        const float fac1 = ex2f(m1 - mn1);

        unsigned pA[4][4];
        float ls0 = 0.f, ls1 = 0.f;
#pragma unroll
        for (int t = 0; t < 4; t++) {
            float p00 = ex2f(s[2*t][0] - mn0),   p01 = ex2f(s[2*t][1] - mn0);
            float p02 = ex2f(s[2*t][2] - mn1),   p03 = ex2f(s[2*t][3] - mn1);
            float p10 = ex2f(s[2*t+1][0] - mn0), p11 = ex2f(s[2*t+1][1] - mn0);
            float p12 = ex2f(s[2*t+1][2] - mn1), p13 = ex2f(s[2*t+1][3] - mn1);
            ls0 += (p00 + p01) + (p10 + p11);
            ls1 += (p02 + p03) + (p12 + p13);
            pA[t][0] = cvt2_f16(p00, p01);
            pA[t][1] = cvt2_f16(p02, p03);
            pA[t][2] = cvt2_f16(p10, p11);
            pA[t][3] = cvt2_f16(p12, p13);
        }
        l0 = l0 * fac0 + ls0;
        l1 = l1 * fac1 + ls1;
        m0 = mn0; m1 = mn1;
#pragma unroll
        for (int n = 0; n < 16; n++) {
            o[n][0] *= fac0; o[n][1] *= fac0;
            o[n][2] *= fac1; o[n][3] *= fac1;
        }

        // ---- O += P @ V : single-term fp16 ----
#pragma unroll
        for (int t = 0; t < 4; t++) {
#pragma unroll
            for (int h = 0; h < 2; h++) {
                unsigned vr[4][4];
#pragma unroll
                for (int g4 = 0; g4 < 4; g4++) {
                    const int g = h * 4 + g4;
                    unsigned boff = (unsigned)((g * 16 + b_n_off) * FL_VROWB + (t * 16 + b_k_off) * 2);
                    ldsm_x4(vB + boff, vr[g4][0], vr[g4][1], vr[g4][2], vr[g4][3]);
                }
#pragma unroll
                for (int g4 = 0; g4 < 4; g4++) {
                    const int g = h * 4 + g4;
                    mma_f16(o[2*g],   pA[t], vr[g4]);
                    mma_f16(o[2*g+1], pA[t], vr[g4] + 2);
                }
            }
        }
    }

    // ---- epilogue ----
    l0 += __shfl_xor_sync(0xffffffffu, l0, 1);
    l0 += __shfl_xor_sync(0xffffffffu, l0, 2);
    l1 += __shfl_xor_sync(0xffffffffu, l1, 1);
    l1 += __shfl_xor_sync(0xffffffffu, l1, 2);

    const int r0 = wm * 16 + (lane >> 2);
    float* __restrict__ Og = g_O[sp] + (qrow0) * HEAD;
#pragma unroll
    for (int n = 0; n < 16; n++) {
        const int col = n * 8 + (lane & 3) * 2;
        *(float2*)&Og[(long)r0 * HEAD + col]       = make_float2(o[n][0], o[n][1]);
        *(float2*)&Og[(long)(r0 + 8) * HEAD + col] = make_float2(o[n][2], o[n][3]);
    }
    if ((lane & 3) == 0) {
        const long rowg = (long)b * SEQ + qt * 128 + r0;
        g_m[sp][rowg] = m0;     g_l[sp][rowg] = l0;
        g_m[sp][rowg + 8] = m1; g_l[sp][rowg + 8] = l1;
    }
}

// ---------------------------------------------------------------------------
// Combine 4 splits (base-2 weights), float4 vectorized.
// ---------------------------------------------------------------------------
__global__ __launch_bounds__(256) void combine_kernel(float* __restrict__ out)
{
    const int id = blockIdx.x * 256 + threadIdx.x;
    const long base = (long)id * 4;
    const int row = (int)(base >> 7);

    float mv[NSPLIT], lv[NSPLIT];
    float M = -1e30f;
#pragma unroll
    for (int s = 0; s < NSPLIT; s++) {
        mv[s] = g_m[s][row];
        lv[s] = g_l[s][row];
        M = fmaxf(M, mv[s]);
    }
    float4 num = make_float4(0.f, 0.f, 0.f, 0.f);
    float den = 0.f;
#pragma unroll
    for (int s = 0; s < NSPLIT; s++) {
        float w = ex2f(mv[s] - M);
        float4 ov = *(const float4*)&g_O[s][base];
        num.x += w * ov.x; num.y += w * ov.y;
        num.z += w * ov.z; num.w += w * ov.w;
        den += w * lv[s];
    }
    float inv = 1.0f / den;
    *(float4*)&out[base] = make_float4(num.x*inv, num.y*inv, num.z*inv, num.w*inv);
}

// ---------------------------------------------------------------------------
extern "C" void kernel_launch(void* const* d_in, const int* in_sizes, int n_in,
                              void* d_out, int out_size)
{
    const float* X  = (const float*)d_in[0];
    const float* WQ = (const float*)d_in[1];
    const float* WK = (const float*)d_in[2];
    const float* WV = (const float*)d_in[3];
    float* out = (float*)d_out;

    cudaFuncSetAttribute(proj_mma_kernel,
                         cudaFuncAttributeMaxDynamicSharedMemorySize, PJ_SMEM);
    cudaFuncSetAttribute(flash_kernel,
                         cudaFuncAttributeMaxDynamicSharedMemorySize, FL_SMEM);

    convert_x_kernel<<<(BATCH*SEQ*EMB)/1024, 256>>>(X);                  // 0
    convert_wv_kernel<<<(384*EMB)/1024, 256>>>(WQ, WK, WV);              // 1
    proj_mma_kernel<<<dim3(64, 2), 256, PJ_SMEM>>>();                    // 2
    flash_kernel<<<BATCH * 16 * NSPLIT, 256, FL_SMEM>>>();               // 3
    combine_kernel<<<(BATCH*SEQ*HEAD/4)/256, 256>>>(out);                // 4
}